// round 6
// baseline (speedup 1.0000x reference)
#include <cuda_runtime.h>
#include <cuda_fp16.h>
#include <cstdint>

#define IN_F   4096
#define OUT_F  4096
#define M_ROWS 8192

// fp16 scratch: merged effective weight and converted activations.
__device__ __half g_Wh[(size_t)OUT_F * IN_F];
__device__ __half g_Xh[(size_t)M_ROWS * IN_F];

__constant__ float NF4[16] = {
    -1.0f, -0.6961928009986877f, -0.5250730514526367f, -0.39491748809814453f,
    -0.28444138169288635f, -0.18477343022823334f, -0.09105003625154495f, 0.0f,
    0.07958029955625534f, 0.16093020141124725f, 0.24611230194568634f,
    0.33791524171829224f, 0.4407098889350891f, 0.5626170039176941f,
    0.7229568362236023f, 1.0f
};

__device__ __forceinline__ uint32_t smem_u32(const void* p) {
    uint32_t a;
    asm("{ .reg .u64 t; cvta.to.shared.u64 t, %1; cvt.u32.u64 %0, t; }" : "=r"(a) : "l"(p));
    return a;
}

// ---------------------------------------------------------------------------
// Kernel A: convert x (fp32) -> g_Xh (fp16). 8 elems/thread.
// ---------------------------------------------------------------------------
__global__ void convert_x_kernel(const float* __restrict__ x) {
    size_t i = ((size_t)blockIdx.x * 256 + threadIdx.x) * 8;
    float4 v0 = *(const float4*)(x + i);
    float4 v1 = *(const float4*)(x + i + 4);
    __half2 h0 = __floats2half2_rn(v0.x, v0.y);
    __half2 h1 = __floats2half2_rn(v0.z, v0.w);
    __half2 h2 = __floats2half2_rn(v1.x, v1.y);
    __half2 h3 = __floats2half2_rn(v1.z, v1.w);
    uint4 o;
    o.x = *(uint32_t*)&h0; o.y = *(uint32_t*)&h1;
    o.z = *(uint32_t*)&h2; o.w = *(uint32_t*)&h3;
    *(uint4*)&g_Xh[i] = o;
}

// ---------------------------------------------------------------------------
// Kernel B: W_eff = NF4 dequant * absmax + lora_B @ lora_A  (fp16 out)
// ---------------------------------------------------------------------------
__global__ void build_weff_kernel(const int* __restrict__ qweight,
                                  const float* __restrict__ absmax,
                                  const float* __restrict__ lA,
                                  const float* __restrict__ lB) {
    __shared__ float Bsh[64][64];
    __shared__ float Ash[64][128];

    const int tid = threadIdx.x;
    const int o0 = blockIdx.y * 64;
    const int i0 = blockIdx.x * 128;

    for (int t = tid; t < 64 * 64; t += 256) {
        int o = t >> 6, r = t & 63;
        Bsh[r][o] = lB[(o0 + o) * 64 + r];
    }
    for (int t = tid; t < 64 * 128; t += 256) {
        int r = t >> 7, c = t & 127;
        Ash[r][c] = lA[r * IN_F + i0 + c];
    }
    __syncthreads();

    const int oo0 = (tid >> 4) * 4;
    const int ii0 = (tid & 15) * 8;

    float acc[4][8];
#pragma unroll
    for (int a = 0; a < 4; a++)
#pragma unroll
        for (int b = 0; b < 8; b++) acc[a][b] = 0.0f;

#pragma unroll 4
    for (int r = 0; r < 64; r++) {
        float4 a0 = *(const float4*)&Ash[r][ii0];
        float4 a1 = *(const float4*)&Ash[r][ii0 + 4];
#pragma unroll
        for (int oo = 0; oo < 4; oo++) {
            float bv = Bsh[r][oo0 + oo];
            acc[oo][0] += bv * a0.x; acc[oo][1] += bv * a0.y;
            acc[oo][2] += bv * a0.z; acc[oo][3] += bv * a0.w;
            acc[oo][4] += bv * a1.x; acc[oo][5] += bv * a1.y;
            acc[oo][6] += bv * a1.z; acc[oo][7] += bv * a1.w;
        }
    }

#pragma unroll
    for (int oo = 0; oo < 4; oo++) {
        const int o = o0 + oo0 + oo;
        const size_t k = (size_t)o * IN_F + i0 + ii0;
        const int4 qv = ((const int4*)qweight)[k >> 3];
        const float am = absmax[k >> 6];

        float w[8];
        w[0] = NF4[qv.x & 15];  w[1] = NF4[(qv.x >> 4) & 15];
        w[2] = NF4[qv.y & 15];  w[3] = NF4[(qv.y >> 4) & 15];
        w[4] = NF4[qv.z & 15];  w[5] = NF4[(qv.z >> 4) & 15];
        w[6] = NF4[qv.w & 15];  w[7] = NF4[(qv.w >> 4) & 15];

        __half2 h0 = __floats2half2_rn(w[0] * am + acc[oo][0], w[1] * am + acc[oo][1]);
        __half2 h1 = __floats2half2_rn(w[2] * am + acc[oo][2], w[3] * am + acc[oo][3]);
        __half2 h2 = __floats2half2_rn(w[4] * am + acc[oo][4], w[5] * am + acc[oo][5]);
        __half2 h3 = __floats2half2_rn(w[6] * am + acc[oo][6], w[7] * am + acc[oo][7]);
        uint4 pk;
        pk.x = *(uint32_t*)&h0; pk.y = *(uint32_t*)&h1;
        pk.z = *(uint32_t*)&h2; pk.w = *(uint32_t*)&h3;
        *(uint4*)&g_Wh[k] = pk;
    }
}

// ---------------------------------------------------------------------------
// Kernel C: persistent fp16 mma.sync GEMM  out[8192,4096] = g_Xh @ g_Wh^T
// BM=128, BN=256, BK=64 (128B swizzled rows), 4-stage cp.async, 256 threads.
// Warp grid 2(m) x 4(n); warp tile 64x64; fragment double-buffering across q.
// ---------------------------------------------------------------------------
constexpr int BM = 128, BN = 256, BK = 64, S = 4;
constexpr int NT = IN_F / BK;                   // 64 k-tiles
constexpr int A_BYTES = BM * 128;               // 16384
constexpr int B_BYTES = BN * 128;               // 32768
constexpr int STAGE = A_BYTES + B_BYTES;        // 49152
constexpr int SMEM_TOTAL = 1024 + S * STAGE;    // 197632
constexpr int TOTAL_TILES = (M_ROWS / BM) * (OUT_F / BN);  // 1024

__device__ __forceinline__ void mma_f16(float c[4], const uint32_t a[4],
                                        uint32_t b0, uint32_t b1) {
    asm volatile(
        "mma.sync.aligned.m16n8k16.row.col.f32.f16.f16.f32 "
        "{%0,%1,%2,%3}, {%4,%5,%6,%7}, {%8,%9}, {%0,%1,%2,%3};"
        : "+f"(c[0]), "+f"(c[1]), "+f"(c[2]), "+f"(c[3])
        : "r"(a[0]), "r"(a[1]), "r"(a[2]), "r"(a[3]), "r"(b0), "r"(b1));
}

__device__ __forceinline__ void ldsm4(uint32_t& r0, uint32_t& r1,
                                      uint32_t& r2, uint32_t& r3, uint32_t addr) {
    asm volatile("ldmatrix.sync.aligned.m8n8.x4.shared.b16 {%0,%1,%2,%3}, [%4];"
                 : "=r"(r0), "=r"(r1), "=r"(r2), "=r"(r3) : "r"(addr));
}

__device__ __forceinline__ void st_cs_f2(float* p, float a, float b) {
    asm volatile("st.global.cs.v2.f32 [%0], {%1,%2};" :: "l"(p), "f"(a), "f"(b)
                 : "memory");
}

// cp.async one stage: A 1024 + B 2048 16B-chunks, 256 threads (12 per thread).
__device__ __forceinline__ void issue_stage(uint32_t sA, uint32_t sB,
                                            const __half* xb, const __half* wb,
                                            int tid) {
#pragma unroll
    for (int r = 0; r < 4; r++) {
        int i = tid + r * 256;
        int row = i >> 3, c = i & 7;
        uint32_t off = (uint32_t)(row * 128 + ((c * 16) ^ ((row & 7) << 4)));
        const __half* src = xb + (size_t)row * IN_F + c * 8;
        asm volatile("cp.async.cg.shared.global.L2::256B [%0], [%1], 16;\n"
                     :: "r"(sA + off), "l"(src));
    }
#pragma unroll
    for (int r = 0; r < 8; r++) {
        int i = tid + r * 256;
        int row = i >> 3, c = i & 7;
        uint32_t off = (uint32_t)(row * 128 + ((c * 16) ^ ((row & 7) << 4)));
        const __half* src = wb + (size_t)row * IN_F + c * 8;
        asm volatile("cp.async.cg.shared.global.L2::256B [%0], [%1], 16;\n"
                     :: "r"(sB + off), "l"(src));
    }
}

__global__ void __launch_bounds__(256, 1)
gemm_f16_kernel(float* __restrict__ out) {
    extern __shared__ char sm[];
    const uint32_t stage0 = (smem_u32(sm) + 1023) & ~1023u;

    const int tid = threadIdx.x;
    const int wid = tid >> 5;
    const int lane = tid & 31;
    const int warp_m = wid & 1;        // 0..1 -> 64 rows
    const int warp_n = wid >> 1;       // 0..3 -> 64 cols
    const int g = lane >> 3;           // ldmatrix tile group 0..3
    const int r = lane & 7;

    // A (mf=0..3): row = warp_m*64 + mf*16 + (g&1)*8 + r ; kconst = (g>>1)*16
    uint32_t a_rowoff[4], a_xr[4];
    const uint32_t a_kc = (uint32_t)((g >> 1) * 16);
#pragma unroll
    for (int mf = 0; mf < 4; mf++) {
        int row = warp_m * 64 + mf * 16 + (g & 1) * 8 + r;
        a_rowoff[mf] = row * 128;
        a_xr[mf] = (row & 7) << 4;
    }
    // B (pair p=0..3): row = warp_n*64 + p*16 + (g>>1)*8 + r ; kconst = (g&1)*16
    uint32_t b_rowoff[4], b_xr[4];
    const uint32_t b_kc = (uint32_t)((g & 1) * 16);
#pragma unroll
    for (int p = 0; p < 4; p++) {
        int row = warp_n * 64 + p * 16 + (g >> 1) * 8 + r;
        b_rowoff[p] = row * 128;
        b_xr[p] = (row & 7) << 4;
    }

    for (int t = blockIdx.x; t < TOTAL_TILES; t += gridDim.x) {
        const int mBase = (t >> 4) * BM;
        const int nBase = (t & 15) * BN;
        const __half* xt = g_Xh + (size_t)mBase * IN_F;
        const __half* wt = g_Wh + (size_t)nBase * IN_F;

        float acc[4][8][4];
#pragma unroll
        for (int i = 0; i < 4; i++)
#pragma unroll
            for (int j = 0; j < 8; j++)
#pragma unroll
                for (int l = 0; l < 4; l++) acc[i][j][l] = 0.0f;

        // prologue: stages 0..S-2
#pragma unroll
        for (int p = 0; p < S - 1; p++) {
            uint32_t sA = stage0 + p * STAGE;
            issue_stage(sA, sA + A_BYTES, xt + p * BK, wt + p * BK, tid);
            asm volatile("cp.async.commit_group;\n" ::: "memory");
        }

        for (int kt = 0; kt < NT; kt++) {
            asm volatile("cp.async.wait_group %0;\n" :: "n"(S - 2) : "memory");
            __syncthreads();

            const uint32_t sA = stage0 + (kt % S) * STAGE;
            const uint32_t sB = sA + A_BYTES;

            // Double-buffered fragments: load q while q-1 computes.
            uint32_t a[2][4][4], b[2][8][2];

            // load q=0 into buffer 0
#pragma unroll
            for (int mf = 0; mf < 4; mf++)
                ldsm4(a[0][mf][0], a[0][mf][1], a[0][mf][2], a[0][mf][3],
                      sA + a_rowoff[mf] + (a_kc ^ a_xr[mf]));
#pragma unroll
            for (int p = 0; p < 4; p++)
                ldsm4(b[0][2 * p][0], b[0][2 * p][1],
                      b[0][2 * p + 1][0], b[0][2 * p + 1][1],
                      sB + b_rowoff[p] + (b_kc ^ b_xr[p]));

            // issue next stage's cp.async while fragments arrive
            if (kt + S - 1 < NT) {
                const int s2 = (kt + S - 1) % S;
                uint32_t nA = stage0 + s2 * STAGE;
                issue_stage(nA, nA + A_BYTES,
                            xt + (kt + S - 1) * BK, wt + (kt + S - 1) * BK, tid);
            }
            asm volatile("cp.async.commit_group;\n" ::: "memory");

#pragma unroll
            for (int q = 0; q < 4; q++) {
                const int cur = q & 1, nxt = cur ^ 1;
                if (q < 3) {
                    const uint32_t kq = (uint32_t)((q + 1) * 32);
#pragma unroll
                    for (int mf = 0; mf < 4; mf++)
                        ldsm4(a[nxt][mf][0], a[nxt][mf][1],
                              a[nxt][mf][2], a[nxt][mf][3],
                              sA + a_rowoff[mf] + ((kq + a_kc) ^ a_xr[mf]));
#pragma unroll
                    for (int p = 0; p < 4; p++)
                        ldsm4(b[nxt][2 * p][0], b[nxt][2 * p][1],
                              b[nxt][2 * p + 1][0], b[nxt][2 * p + 1][1],
                              sB + b_rowoff[p] + ((kq + b_kc) ^ b_xr[p]));
                }
#pragma unroll
                for (int mf = 0; mf < 4; mf++)
#pragma unroll
                    for (int nf = 0; nf < 8; nf++)
                        mma_f16(acc[mf][nf], a[cur][mf],
                                b[cur][nf][0], b[cur][nf][1]);
            }
        }
        asm volatile("cp.async.wait_group 0;\n" ::: "memory");

        // epilogue: direct evict-first STG from accumulators
#pragma unroll
        for (int mf = 0; mf < 4; mf++) {
#pragma unroll
            for (int nf = 0; nf < 8; nf++) {
                const int row = mBase + warp_m * 64 + mf * 16 + (lane >> 2);
                const int col = nBase + warp_n * 64 + nf * 8 + (lane & 3) * 2;
                st_cs_f2(&out[(size_t)row * OUT_F + col],
                         acc[mf][nf][0], acc[mf][nf][1]);
                st_cs_f2(&out[(size_t)(row + 8) * OUT_F + col],
                         acc[mf][nf][2], acc[mf][nf][3]);
            }
        }
        __syncthreads();   // all warps done with smem before next tile prologue
    }
}

// ---------------------------------------------------------------------------
extern "C" void kernel_launch(void* const* d_in, const int* in_sizes, int n_in,
                              void* d_out, int out_size) {
    const float* x  = (const float*)d_in[0];
    const int*   qw = (const int*)d_in[1];
    const float* am = (const float*)d_in[2];
    const float* lA = (const float*)d_in[3];
    const float* lB = (const float*)d_in[4];
    float*       out = (float*)d_out;

    (void)in_sizes; (void)n_in; (void)out_size;

    cudaFuncSetAttribute(gemm_f16_kernel,
                         cudaFuncAttributeMaxDynamicSharedMemorySize, SMEM_TOTAL);

    convert_x_kernel<<<(M_ROWS * IN_F / 8) / 256, 256>>>(x);
    build_weff_kernel<<<dim3(IN_F / 128, OUT_F / 64), 256>>>(qw, am, lA, lB);
    gemm_f16_kernel<<<148, 256, SMEM_TOTAL>>>(out);
}

// round 7
// speedup vs baseline: 1.7293x; 1.7293x over previous
#include <cuda_runtime.h>
#include <cuda_fp16.h>
#include <cstdint>
#include <cstdio>
#include <cstring>
#include <cmath>
#include <dlfcn.h>

#define IN_F   4096
#define OUT_F  4096
#define M_ROWS 8192

// Host-module fp16 scratch (used by the fallback path).
__device__ __half g_Xh[(size_t)M_ROWS * IN_F];
__device__ __half g_Wh[(size_t)OUT_F * IN_F];

__constant__ float NF4[16] = {
    -1.0f, -0.6961928009986877f, -0.5250730514526367f, -0.39491748809814453f,
    -0.28444138169288635f, -0.18477343022823334f, -0.09105003625154495f, 0.0f,
    0.07958029955625534f, 0.16093020141124725f, 0.24611230194568634f,
    0.33791524171829224f, 0.4407098889350891f, 0.5626170039176941f,
    0.7229568362236023f, 1.0f
};

__device__ __forceinline__ uint32_t smem_u32(const void* p) {
    uint32_t a;
    asm("{ .reg .u64 t; cvta.to.shared.u64 t, %1; cvt.u32.u64 %0, t; }" : "=r"(a) : "l"(p));
    return a;
}

// ---------------------------------------------------------------------------
// Kernel A: convert x (fp32) -> dst (fp16). 8 elems/thread.
// ---------------------------------------------------------------------------
__global__ void convert_x_kernel(const float* __restrict__ x, __half* __restrict__ dst) {
    size_t i = ((size_t)blockIdx.x * 256 + threadIdx.x) * 8;
    float4 v0 = *(const float4*)(x + i);
    float4 v1 = *(const float4*)(x + i + 4);
    __half2 h0 = __floats2half2_rn(v0.x, v0.y);
    __half2 h1 = __floats2half2_rn(v0.z, v0.w);
    __half2 h2 = __floats2half2_rn(v1.x, v1.y);
    __half2 h3 = __floats2half2_rn(v1.z, v1.w);
    uint4 o;
    o.x = *(uint32_t*)&h0; o.y = *(uint32_t*)&h1;
    o.z = *(uint32_t*)&h2; o.w = *(uint32_t*)&h3;
    *(uint4*)&dst[i] = o;
}

// ---------------------------------------------------------------------------
// Kernel B: W_eff = NF4 dequant * absmax + lora_B @ lora_A  (fp16 out)
// ---------------------------------------------------------------------------
__global__ void build_weff_kernel(const int* __restrict__ qweight,
                                  const float* __restrict__ absmax,
                                  const float* __restrict__ lA,
                                  const float* __restrict__ lB,
                                  __half* __restrict__ dst) {
    __shared__ float Bsh[64][64];
    __shared__ float Ash[64][128];

    const int tid = threadIdx.x;
    const int o0 = blockIdx.y * 64;
    const int i0 = blockIdx.x * 128;

    for (int t = tid; t < 64 * 64; t += 256) {
        int o = t >> 6, r = t & 63;
        Bsh[r][o] = lB[(o0 + o) * 64 + r];
    }
    for (int t = tid; t < 64 * 128; t += 256) {
        int r = t >> 7, c = t & 127;
        Ash[r][c] = lA[r * IN_F + i0 + c];
    }
    __syncthreads();

    const int oo0 = (tid >> 4) * 4;
    const int ii0 = (tid & 15) * 8;

    float acc[4][8];
#pragma unroll
    for (int a = 0; a < 4; a++)
#pragma unroll
        for (int b = 0; b < 8; b++) acc[a][b] = 0.0f;

#pragma unroll 4
    for (int r = 0; r < 64; r++) {
        float4 a0 = *(const float4*)&Ash[r][ii0];
        float4 a1 = *(const float4*)&Ash[r][ii0 + 4];
#pragma unroll
        for (int oo = 0; oo < 4; oo++) {
            float bv = Bsh[r][oo0 + oo];
            acc[oo][0] += bv * a0.x; acc[oo][1] += bv * a0.y;
            acc[oo][2] += bv * a0.z; acc[oo][3] += bv * a0.w;
            acc[oo][4] += bv * a1.x; acc[oo][5] += bv * a1.y;
            acc[oo][6] += bv * a1.z; acc[oo][7] += bv * a1.w;
        }
    }

#pragma unroll
    for (int oo = 0; oo < 4; oo++) {
        const int o = o0 + oo0 + oo;
        const size_t k = (size_t)o * IN_F + i0 + ii0;
        const int4 qv = ((const int4*)qweight)[k >> 3];
        const float am = absmax[k >> 6];

        float w[8];
        w[0] = NF4[qv.x & 15];  w[1] = NF4[(qv.x >> 4) & 15];
        w[2] = NF4[qv.y & 15];  w[3] = NF4[(qv.y >> 4) & 15];
        w[4] = NF4[qv.z & 15];  w[5] = NF4[(qv.z >> 4) & 15];
        w[6] = NF4[qv.w & 15];  w[7] = NF4[(qv.w >> 4) & 15];

        __half2 h0 = __floats2half2_rn(w[0] * am + acc[oo][0], w[1] * am + acc[oo][1]);
        __half2 h1 = __floats2half2_rn(w[2] * am + acc[oo][2], w[3] * am + acc[oo][3]);
        __half2 h2 = __floats2half2_rn(w[4] * am + acc[oo][4], w[5] * am + acc[oo][5]);
        __half2 h3 = __floats2half2_rn(w[6] * am + acc[oo][6], w[7] * am + acc[oo][7]);
        uint4 pk;
        pk.x = *(uint32_t*)&h0; pk.y = *(uint32_t*)&h1;
        pk.z = *(uint32_t*)&h2; pk.w = *(uint32_t*)&h3;
        *(uint4*)&dst[k] = pk;
    }
}

// ---------------------------------------------------------------------------
// Fallback kernel C (proven 778us): fp16 mma.sync GEMM, 512 thr, 4-stage.
// ---------------------------------------------------------------------------
constexpr int BM = 128, BN = 256, BK = 64, S = 4;
constexpr int NT = IN_F / BK;
constexpr int A_BYTES = BM * 128;
constexpr int B_BYTES = BN * 128;
constexpr int STAGE = A_BYTES + B_BYTES;
constexpr int SMEM_TOTAL = 1024 + S * STAGE;
constexpr int TOTAL_TILES = (M_ROWS / BM) * (OUT_F / BN);

__device__ __forceinline__ void mma_f16(float c[4], const uint32_t a[4],
                                        uint32_t b0, uint32_t b1) {
    asm volatile(
        "mma.sync.aligned.m16n8k16.row.col.f32.f16.f16.f32 "
        "{%0,%1,%2,%3}, {%4,%5,%6,%7}, {%8,%9}, {%0,%1,%2,%3};"
        : "+f"(c[0]), "+f"(c[1]), "+f"(c[2]), "+f"(c[3])
        : "r"(a[0]), "r"(a[1]), "r"(a[2]), "r"(a[3]), "r"(b0), "r"(b1));
}

__device__ __forceinline__ void ldsm4(uint32_t& r0, uint32_t& r1,
                                      uint32_t& r2, uint32_t& r3, uint32_t addr) {
    asm volatile("ldmatrix.sync.aligned.m8n8.x4.shared.b16 {%0,%1,%2,%3}, [%4];"
                 : "=r"(r0), "=r"(r1), "=r"(r2), "=r"(r3) : "r"(addr));
}

__device__ __forceinline__ void st_cs_f2(float* p, float a, float b) {
    asm volatile("st.global.cs.v2.f32 [%0], {%1,%2};" :: "l"(p), "f"(a), "f"(b)
                 : "memory");
}

__device__ __forceinline__ void issue_stage(uint32_t sA, uint32_t sB,
                                            const __half* xb, const __half* wb,
                                            int tid) {
#pragma unroll
    for (int r = 0; r < 2; r++) {
        int i = tid + r * 512;
        int row = i >> 3, c = i & 7;
        uint32_t off = (uint32_t)(row * 128 + ((c * 16) ^ ((row & 7) << 4)));
        const __half* src = xb + (size_t)row * IN_F + c * 8;
        asm volatile("cp.async.cg.shared.global.L2::256B [%0], [%1], 16;\n"
                     :: "r"(sA + off), "l"(src));
    }
#pragma unroll
    for (int r = 0; r < 4; r++) {
        int i = tid + r * 512;
        int row = i >> 3, c = i & 7;
        uint32_t off = (uint32_t)(row * 128 + ((c * 16) ^ ((row & 7) << 4)));
        const __half* src = wb + (size_t)row * IN_F + c * 8;
        asm volatile("cp.async.cg.shared.global.L2::256B [%0], [%1], 16;\n"
                     :: "r"(sB + off), "l"(src));
    }
}

__global__ void __launch_bounds__(512, 1)
gemm_f16_kernel(const __half* __restrict__ Xh, const __half* __restrict__ Wh,
                float* __restrict__ out) {
    extern __shared__ char sm[];
    const uint32_t stage0 = (smem_u32(sm) + 1023) & ~1023u;

    const int tid = threadIdx.x;
    const int wid = tid >> 5;
    const int lane = tid & 31;
    const int warp_m = wid & 3;
    const int warp_n = wid >> 2;
    const int g = lane >> 3;
    const int r = lane & 7;

    uint32_t a_rowoff[2], a_xr[2];
    const uint32_t a_kc = (uint32_t)((g >> 1) * 16);
#pragma unroll
    for (int mf = 0; mf < 2; mf++) {
        int row = warp_m * 32 + mf * 16 + (g & 1) * 8 + r;
        a_rowoff[mf] = row * 128;
        a_xr[mf] = (row & 7) << 4;
    }
    uint32_t b_rowoff[4], b_xr[4];
    const uint32_t b_kc = (uint32_t)((g & 1) * 16);
#pragma unroll
    for (int p = 0; p < 4; p++) {
        int row = warp_n * 64 + p * 16 + (g >> 1) * 8 + r;
        b_rowoff[p] = row * 128;
        b_xr[p] = (row & 7) << 4;
    }

    for (int t = blockIdx.x; t < TOTAL_TILES; t += gridDim.x) {
        const int mBase = (t >> 4) * BM;
        const int nBase = (t & 15) * BN;
        const __half* xt = Xh + (size_t)mBase * IN_F;
        const __half* wt = Wh + (size_t)nBase * IN_F;

        float acc[2][8][4];
#pragma unroll
        for (int i = 0; i < 2; i++)
#pragma unroll
            for (int j = 0; j < 8; j++)
#pragma unroll
                for (int l = 0; l < 4; l++) acc[i][j][l] = 0.0f;

#pragma unroll
        for (int p = 0; p < S - 1; p++) {
            uint32_t sA = stage0 + p * STAGE;
            issue_stage(sA, sA + A_BYTES, xt + p * BK, wt + p * BK, tid);
            asm volatile("cp.async.commit_group;\n" ::: "memory");
        }

        for (int kt = 0; kt < NT; kt++) {
            asm volatile("cp.async.wait_group %0;\n" :: "n"(S - 2) : "memory");
            __syncthreads();

            if (kt + S - 1 < NT) {
                const int s2 = (kt + S - 1) % S;
                uint32_t sA = stage0 + s2 * STAGE;
                issue_stage(sA, sA + A_BYTES,
                            xt + (kt + S - 1) * BK, wt + (kt + S - 1) * BK, tid);
            }
            asm volatile("cp.async.commit_group;\n" ::: "memory");

            const uint32_t sA = stage0 + (kt % S) * STAGE;
            const uint32_t sB = sA + A_BYTES;

#pragma unroll
            for (int q = 0; q < 4; q++) {
                uint32_t a[2][4];
#pragma unroll
                for (int mf = 0; mf < 2; mf++)
                    ldsm4(a[mf][0], a[mf][1], a[mf][2], a[mf][3],
                          sA + a_rowoff[mf] + (((q * 32) + a_kc) ^ a_xr[mf]));
                uint32_t b[8][2];
#pragma unroll
                for (int p = 0; p < 4; p++)
                    ldsm4(b[2 * p][0], b[2 * p][1], b[2 * p + 1][0], b[2 * p + 1][1],
                          sB + b_rowoff[p] + (((q * 32) + b_kc) ^ b_xr[p]));
#pragma unroll
                for (int mf = 0; mf < 2; mf++)
#pragma unroll
                    for (int nf = 0; nf < 8; nf++)
                        mma_f16(acc[mf][nf], a[mf], b[nf][0], b[nf][1]);
            }
        }
        asm volatile("cp.async.wait_group 0;\n" ::: "memory");

#pragma unroll
        for (int mf = 0; mf < 2; mf++) {
#pragma unroll
            for (int nf = 0; nf < 8; nf++) {
                const int row = mBase + warp_m * 32 + mf * 16 + (lane >> 2);
                const int col = nBase + warp_n * 64 + nf * 8 + (lane & 3) * 2;
                st_cs_f2(&out[(size_t)row * OUT_F + col],
                         acc[mf][nf][0], acc[mf][nf][1]);
                st_cs_f2(&out[(size_t)(row + 8) * OUT_F + col],
                         acc[mf][nf][2], acc[mf][nf][3]);
            }
        }
        __syncthreads();
    }
}

// ===========================================================================
// NVRTC tcgen05 path
// ===========================================================================
static const char* NVRTC_SRC = R"NVSRC(
typedef unsigned int u32;
typedef unsigned long long u64;

__device__ unsigned short GX[33554432];   // 8192*4096 fp16
__device__ unsigned short GW[16777216];   // 4096*4096 fp16
__device__ float GOUT[33554432];          // 8192*4096 fp32 (self-test only)

extern "C" __global__ void initt() {
    u64 i = (u64)blockIdx.x * 256 + threadIdx.x;
    const unsigned short T[9] = {0xBC00,0xBA00,0xB800,0xB400,0,0x3400,0x3800,0x3A00,0x3C00};
    if (i < 33554432ull) {
        u32 m = (u32)(i >> 12), k = (u32)(i & 4095);
        GX[i] = T[(k*131u + m*7u) % 9u];
    }
    if (i < 16777216ull) {
        u32 n = (u32)(i >> 12), k = (u32)(i & 4095);
        GW[i] = T[(k*17u + n*3u) % 7u + 1u];
    }
}

__device__ __forceinline__ void ld_stage(u32 sA, u32 sB, const char* xb,
                                         const char* wb, int tid) {
#pragma unroll
    for (int r = 0; r < 4; r++) {
        int i = tid + r * 256; int row = i >> 3, c = i & 7;
        u32 off = (u32)(row * 128 + ((c * 16) ^ ((row & 7) << 4)));
        asm volatile("cp.async.cg.shared.global.L2::256B [%0], [%1], 16;"
                     :: "r"(sA + off), "l"(xb + (u64)row * 8192 + c * 16));
    }
#pragma unroll
    for (int r = 0; r < 8; r++) {
        int i = tid + r * 256; int row = i >> 3, c = i & 7;
        u32 off = (u32)(row * 128 + ((c * 16) ^ ((row & 7) << 4)));
        asm volatile("cp.async.cg.shared.global.L2::256B [%0], [%1], 16;"
                     :: "r"(sB + off), "l"(wb + (u64)row * 8192 + c * 16));
    }
}

extern "C" __global__ void __launch_bounds__(256, 1)
gemm5(const char* __restrict__ X, const char* __restrict__ W,
      float* __restrict__ out) {
    extern __shared__ char sm[];
    u32 base;
    { u32 a; asm("{ .reg .u64 t; cvta.to.shared.u64 t, %1; cvt.u32.u64 %0, t; }"
                 : "=r"(a) : "l"((void*)sm)); base = (a + 1023) & ~1023u; }
    const u32 tptr = base;
    const u32 mb = base + 16;
    const u32 st0 = base + 1024;
    const int tid = threadIdx.x, wid = tid >> 5, lid = tid & 31;

    if (wid == 0)
        asm volatile("tcgen05.alloc.cta_group::1.sync.aligned.shared::cta.b32 [%0], %1;"
                     :: "r"(tptr), "r"(256u) : "memory");
    if (tid == 0) {
#pragma unroll
        for (int s = 0; s < 4; s++)
            asm volatile("mbarrier.init.shared.b64 [%0], %1;"
                         :: "r"(mb + s * 8), "r"(1u) : "memory");
    }
    __syncthreads();
    u32 tmem; asm volatile("ld.shared.b32 %0,[%1];" : "=r"(tmem) : "r"(tptr));

    const u64 DBASE = (2ull << 61) | (1ull << 46) | (64ull << 32) | (1ull << 16);
    const u32 IDESC = (1u << 4) | (32u << 17) | (8u << 24);

#pragma unroll 1
    for (int t = blockIdx.x; t < 1024; t += gridDim.x) {
        const int mBase = (t >> 4) * 128, nBase = (t & 15) * 256;
        const char* xt = X + (u64)mBase * 8192;
        const char* wt = W + (u64)nBase * 8192;

#pragma unroll
        for (int p = 0; p < 4; p++) {
            u32 sA = st0 + p * 49152;
            ld_stage(sA, sA + 16384, xt + p * 128, wt + p * 128, tid);
            asm volatile("cp.async.commit_group;" ::: "memory");
        }

#pragma unroll 1
        for (int kt = 0; kt < 64; kt++) {
            const int s = kt & 3;
            const u32 sA = st0 + s * 49152, sB = sA + 16384;
            asm volatile("cp.async.wait_group 3;" ::: "memory");
            __syncthreads();

            if (wid == 0) {
                u32 ep;
                asm volatile("{ .reg .pred p; elect.sync _|p, 0xFFFFFFFF; selp.b32 %0,1,0,p; }"
                             : "=r"(ep));
                if (ep) {
                    asm volatile("fence.proxy.async.shared::cta;" ::: "memory");
                    u64 ad = DBASE | ((u64)(sA >> 4) & 0x3FFF);
                    u64 bd = DBASE | ((u64)(sB >> 4) & 0x3FFF);
#pragma unroll
                    for (int q = 0; q < 4; q++) {
                        u32 en = (kt > 0 || q > 0) ? 1u : 0u;
                        asm volatile("{ .reg .pred p; setp.ne.u32 p, %5, 0; "
                            "tcgen05.mma.cta_group::1.kind::f16 [%0], %1, %2, %3, {%4,%4,%4,%4}, p; }"
                            :: "r"(tmem), "l"(ad + q * 2), "l"(bd + q * 2),
                               "r"(IDESC), "r"(0u), "r"(en) : "memory");
                    }
                    asm volatile("tcgen05.commit.cta_group::1.mbarrier::arrive::one.shared::cluster.b64 [%0];"
                                 :: "r"(mb + s * 8) : "memory");
                }
            }

            if (kt + 4 < 64) {
                u32 done; u32 ph = (u32)((kt >> 2) & 1); u32 ba = mb + s * 8;
                asm volatile("{ .reg .pred p; mbarrier.try_wait.parity.acquire.cta.shared::cta.b64 p, [%1], %2; selp.b32 %0,1,0,p; }"
                             : "=r"(done) : "r"(ba), "r"(ph) : "memory");
                if (!done) {
                    asm volatile("{ .reg .pred P1; WLA: mbarrier.try_wait.parity.acquire.cta.shared::cta.b64 P1, [%0], %1, 0x989680; @P1 bra.uni WDA; bra.uni WLA; WDA: }"
                                 :: "r"(ba), "r"(ph) : "memory");
                }
                ld_stage(sA, sB, xt + (kt + 4) * 128, wt + (kt + 4) * 128, tid);
            }
            asm volatile("cp.async.commit_group;" ::: "memory");
        }

        // drain: last commit was on slot 3, parity 1
        {
            u32 done; u32 ba = mb + 24;
            asm volatile("{ .reg .pred p; mbarrier.try_wait.parity.acquire.cta.shared::cta.b64 p, [%1], %2; selp.b32 %0,1,0,p; }"
                         : "=r"(done) : "r"(ba), "r"(1u) : "memory");
            if (!done) {
                asm volatile("{ .reg .pred P1; WLB: mbarrier.try_wait.parity.acquire.cta.shared::cta.b64 P1, [%0], %1, 0x989680; @P1 bra.uni WDB; bra.uni WLB; WDB: }"
                             :: "r"(ba), "r"(1u) : "memory");
            }
        }
        asm volatile("tcgen05.fence::after_thread_sync;" ::: "memory");

        if (wid < 4) {
            float* dst = out + (u64)(mBase + wid * 32 + lid) * 4096 + nBase;
#pragma unroll
            for (int ch = 0; ch < 8; ch++) {
                u32 rr[32];
                asm volatile(
                    "tcgen05.ld.sync.aligned.32x32b.x32.b32 "
                    "{%0,%1,%2,%3,%4,%5,%6,%7,%8,%9,%10,%11,%12,%13,%14,%15,"
                    "%16,%17,%18,%19,%20,%21,%22,%23,%24,%25,%26,%27,%28,%29,%30,%31}, [%32];"
                    : "=r"(rr[0]), "=r"(rr[1]), "=r"(rr[2]), "=r"(rr[3]),
                      "=r"(rr[4]), "=r"(rr[5]), "=r"(rr[6]), "=r"(rr[7]),
                      "=r"(rr[8]), "=r"(rr[9]), "=r"(rr[10]), "=r"(rr[11]),
                      "=r"(rr[12]), "=r"(rr[13]), "=r"(rr[14]), "=r"(rr[15]),
                      "=r"(rr[16]), "=r"(rr[17]), "=r"(rr[18]), "=r"(rr[19]),
                      "=r"(rr[20]), "=r"(rr[21]), "=r"(rr[22]), "=r"(rr[23]),
                      "=r"(rr[24]), "=r"(rr[25]), "=r"(rr[26]), "=r"(rr[27]),
                      "=r"(rr[28]), "=r"(rr[29]), "=r"(rr[30]), "=r"(rr[31])
                    : "r"(tmem + ch * 32));
                asm volatile("tcgen05.wait::ld.sync.aligned;" ::: "memory");
#pragma unroll
                for (int j = 0; j < 8; j++) {
                    asm volatile("st.global.cs.v4.b32 [%0], {%1,%2,%3,%4};"
                                 :: "l"(dst + ch * 32 + j * 4),
                                    "r"(rr[4 * j]), "r"(rr[4 * j + 1]),
                                    "r"(rr[4 * j + 2]), "r"(rr[4 * j + 3]) : "memory");
                }
            }
            asm volatile("tcgen05.fence::before_thread_sync;" ::: "memory");
        }
        __syncthreads();
    }

    __syncthreads();
    if (wid == 0) {
        asm volatile("tcgen05.relinquish_alloc_permit.cta_group::1.sync.aligned;");
        asm volatile("tcgen05.dealloc.cta_group::1.sync.aligned.b32 %0, %1;"
                     :: "r"(tmem), "r"(256u));
    }
}
)NVSRC";

// --- driver/nvrtc plumbing (all dlopen-based; no headers, no link deps) ---
typedef int (*nvrtcCreateProgram_t)(void**, const char*, const char*, int,
                                    const char* const*, const char* const*);
typedef int (*nvrtcCompileProgram_t)(void*, int, const char* const*);
typedef int (*nvrtcGetCUBINSize_t)(void*, size_t*);
typedef int (*nvrtcGetCUBIN_t)(void*, char*);
typedef int (*cuInit_t)(unsigned);
typedef int (*cuDevicePrimaryCtxRetain_t)(void**, int);
typedef int (*cuCtxSetCurrent_t)(void*);
typedef int (*cuModuleLoadDataEx_t)(void**, const void*, unsigned, int*, void**);
typedef int (*cuModuleGetFunction_t)(void**, void*, const char*);
typedef int (*cuModuleGetGlobal_t)(unsigned long long*, size_t*, void*, const char*);
typedef int (*cuFuncSetAttribute_t)(void*, int, int);
typedef int (*cuLaunchKernel_t)(void*, unsigned, unsigned, unsigned,
                                unsigned, unsigned, unsigned,
                                unsigned, void*, void**, void**);
typedef int (*cuCtxSynchronize_t)(void);
typedef int (*cuMemcpyDtoH_t)(void*, unsigned long long, size_t);

#if defined(CUDA_API_PER_THREAD_DEFAULT_STREAM) || defined(__CUDA_API_PER_THREAD_DEFAULT_STREAM)
#define DRV_STREAM ((void*)0x2)
#else
#define DRV_STREAM ((void*)0x1)
#endif

static bool g_drv_ok = false;
static cuLaunchKernel_t p_cuLaunchKernel = nullptr;
static void* g_fn_gemm = nullptr;
static unsigned long long g_gx = 0, g_gw = 0;
constexpr int SMEM5 = 198656;

static bool try_init_tcgen05() {
    void* hcu = dlopen("libcuda.so.1", RTLD_NOW | RTLD_GLOBAL);
    if (!hcu) hcu = dlopen("libcuda.so", RTLD_NOW | RTLD_GLOBAL);
    if (!hcu) return false;
    void* hnv = dlopen("libnvrtc.so.13", RTLD_NOW | RTLD_GLOBAL);
    if (!hnv) hnv = dlopen("libnvrtc.so", RTLD_NOW | RTLD_GLOBAL);
    if (!hnv) hnv = dlopen("libnvrtc.so.12", RTLD_NOW | RTLD_GLOBAL);
    if (!hnv) return false;

    auto nCreate  = (nvrtcCreateProgram_t)dlsym(hnv, "nvrtcCreateProgram");
    auto nCompile = (nvrtcCompileProgram_t)dlsym(hnv, "nvrtcCompileProgram");
    auto nCbSize  = (nvrtcGetCUBINSize_t)dlsym(hnv, "nvrtcGetCUBINSize");
    auto nCb      = (nvrtcGetCUBIN_t)dlsym(hnv, "nvrtcGetCUBIN");
    auto cInit    = (cuInit_t)dlsym(hcu, "cuInit");
    auto cRetain  = (cuDevicePrimaryCtxRetain_t)dlsym(hcu, "cuDevicePrimaryCtxRetain");
    auto cSetCur  = (cuCtxSetCurrent_t)dlsym(hcu, "cuCtxSetCurrent");
    auto cModLoad = (cuModuleLoadDataEx_t)dlsym(hcu, "cuModuleLoadDataEx");
    auto cGetFn   = (cuModuleGetFunction_t)dlsym(hcu, "cuModuleGetFunction");
    auto cGetGlb  = (cuModuleGetGlobal_t)dlsym(hcu, "cuModuleGetGlobal_v2");
    auto cSetAttr = (cuFuncSetAttribute_t)dlsym(hcu, "cuFuncSetAttribute");
    auto cLaunch  = (cuLaunchKernel_t)dlsym(hcu, "cuLaunchKernel");
    auto cSync    = (cuCtxSynchronize_t)dlsym(hcu, "cuCtxSynchronize");
    auto cD2H     = (cuMemcpyDtoH_t)dlsym(hcu, "cuMemcpyDtoH_v2");
    if (!nCreate || !nCompile || !nCbSize || !nCb || !cInit || !cRetain ||
        !cSetCur || !cModLoad || !cGetFn || !cGetGlb || !cSetAttr ||
        !cLaunch || !cSync || !cD2H)
        return false;

    if (cInit(0)) return false;
    void* ctx = nullptr;
    if (cRetain(&ctx, 0)) return false;
    if (cSetCur(ctx)) return false;

    void* prog = nullptr;
    if (nCreate(&prog, NVRTC_SRC, "gemm5.cu", 0, nullptr, nullptr)) return false;
    const char* opts[] = {"--gpu-architecture=sm_103a"};
    if (nCompile(prog, 1, opts)) return false;
    size_t cbsz = 0;
    if (nCbSize(prog, &cbsz) || cbsz == 0) return false;
    static char* cubin = new char[cbsz];
    if (nCb(prog, cubin)) return false;

    void* mod = nullptr;
    if (cModLoad(&mod, cubin, 0, nullptr, nullptr)) return false;
    void* fGemm = nullptr, *fInit = nullptr;
    if (cGetFn(&fGemm, mod, "gemm5")) return false;
    if (cGetFn(&fInit, mod, "initt")) return false;
    unsigned long long gx = 0, gw = 0, gout = 0; size_t sz;
    if (cGetGlb(&gx, &sz, mod, "GX")) return false;
    if (cGetGlb(&gw, &sz, mod, "GW")) return false;
    if (cGetGlb(&gout, &sz, mod, "GOUT")) return false;
    // attr 8 = CU_FUNC_ATTRIBUTE_MAX_DYNAMIC_SHARED_SIZE_BYTES
    if (cSetAttr(fGemm, 8, SMEM5)) return false;

    // ---- self-test: exact integer-grid GEMM ----
    if (cLaunch(fInit, 131072, 1, 1, 256, 1, 1, 0, DRV_STREAM, nullptr, nullptr))
        return false;
    {
        unsigned long long px = gx, pw = gw, po = gout;
        void* args[3] = {&px, &pw, &po};
        if (cLaunch(fGemm, 148, 1, 1, 256, 1, 1, SMEM5, DRV_STREAM, args, nullptr))
            return false;
    }
    if (cSync()) return false;

    static float row[OUT_F];
    const int ms[4] = {0, 97, 4095, 8191};
    for (int ri = 0; ri < 4; ri++) {
        int m = ms[ri];
        if (cD2H(row, gout + (unsigned long long)m * OUT_F * 4, OUT_F * 4))
            return false;
        for (int n = 0; n < OUT_F; n++) {
            float ref = 0.0f;
            for (int k = 0; k < IN_F; k++) {
                int av = (k * 131 + m * 7) % 9 - 4;
                int bv = (k * 17 + n * 3) % 7 - 3;
                ref += (av * 0.25f) * (bv * 0.25f);
            }
            if (fabsf(row[n] - ref) > 0.01f) return false;
        }
    }

    p_cuLaunchKernel = cLaunch;
    g_fn_gemm = fGemm;
    g_gx = gx; g_gw = gw;
    return true;
}

__attribute__((constructor))
static void _init_drv() {
    g_drv_ok = try_init_tcgen05();
}

// ---------------------------------------------------------------------------
extern "C" void kernel_launch(void* const* d_in, const int* in_sizes, int n_in,
                              void* d_out, int out_size) {
    const float* x  = (const float*)d_in[0];
    const int*   qw = (const int*)d_in[1];
    const float* am = (const float*)d_in[2];
    const float* lA = (const float*)d_in[3];
    const float* lB = (const float*)d_in[4];
    float*       out = (float*)d_out;

    (void)in_sizes; (void)n_in; (void)out_size;

    __half* xh;
    __half* wh;
    if (g_drv_ok) {
        xh = (__half*)(uintptr_t)g_gx;
        wh = (__half*)(uintptr_t)g_gw;
    } else {
        cudaGetSymbolAddress((void**)&xh, g_Xh);
        cudaGetSymbolAddress((void**)&wh, g_Wh);
    }

    convert_x_kernel<<<(M_ROWS * IN_F / 8) / 256, 256>>>(x, xh);
    build_weff_kernel<<<dim3(IN_F / 128, OUT_F / 64), 256>>>(qw, am, lA, lB, wh);

    if (g_drv_ok) {
        unsigned long long px = (unsigned long long)(uintptr_t)xh;
        unsigned long long pw = (unsigned long long)(uintptr_t)wh;
        void* po = (void*)out;
        void* args[3] = {&px, &pw, &po};
        p_cuLaunchKernel(g_fn_gemm, 148, 1, 1, 256, 1, 1, SMEM5,
                         DRV_STREAM, args, nullptr);
    } else {
        cudaFuncSetAttribute(gemm_f16_kernel,
                             cudaFuncAttributeMaxDynamicSharedMemorySize, SMEM_TOTAL);
        gemm_f16_kernel<<<148, 512, SMEM_TOTAL>>>(xh, wh, out);
    }
}

// round 8
// speedup vs baseline: 1.8881x; 1.0918x over previous
#include <cuda_runtime.h>
#include <cuda_fp16.h>
#include <cstdint>
#include <cstdio>
#include <cstring>
#include <cmath>
#include <dlfcn.h>

#define IN_F   4096
#define OUT_F  4096
#define M_ROWS 8192

// Host-module fp16 scratch (used by the fallback path).
__device__ __half g_Xh[(size_t)M_ROWS * IN_F];
__device__ __half g_Wh[(size_t)OUT_F * IN_F];

__constant__ float NF4[16] = {
    -1.0f, -0.6961928009986877f, -0.5250730514526367f, -0.39491748809814453f,
    -0.28444138169288635f, -0.18477343022823334f, -0.09105003625154495f, 0.0f,
    0.07958029955625534f, 0.16093020141124725f, 0.24611230194568634f,
    0.33791524171829224f, 0.4407098889350891f, 0.5626170039176941f,
    0.7229568362236023f, 1.0f
};

static const float NF4H[16] = {
    -1.0f, -0.6961928009986877f, -0.5250730514526367f, -0.39491748809814453f,
    -0.28444138169288635f, -0.18477343022823334f, -0.09105003625154495f, 0.0f,
    0.07958029955625534f, 0.16093020141124725f, 0.24611230194568634f,
    0.33791524171829224f, 0.4407098889350891f, 0.5626170039176941f,
    0.7229568362236023f, 1.0f
};

__device__ __forceinline__ uint32_t smem_u32(const void* p) {
    uint32_t a;
    asm("{ .reg .u64 t; cvta.to.shared.u64 t, %1; cvt.u32.u64 %0, t; }" : "=r"(a) : "l"(p));
    return a;
}

// ---------------------------------------------------------------------------
// Kernel A: convert x (fp32) -> dst (fp16). 8 elems/thread.
// ---------------------------------------------------------------------------
__global__ void convert_x_kernel(const float* __restrict__ x, __half* __restrict__ dst) {
    size_t i = ((size_t)blockIdx.x * 256 + threadIdx.x) * 8;
    float4 v0 = *(const float4*)(x + i);
    float4 v1 = *(const float4*)(x + i + 4);
    __half2 h0 = __floats2half2_rn(v0.x, v0.y);
    __half2 h1 = __floats2half2_rn(v0.z, v0.w);
    __half2 h2 = __floats2half2_rn(v1.x, v1.y);
    __half2 h3 = __floats2half2_rn(v1.z, v1.w);
    uint4 o;
    o.x = *(uint32_t*)&h0; o.y = *(uint32_t*)&h1;
    o.z = *(uint32_t*)&h2; o.w = *(uint32_t*)&h3;
    *(uint4*)&dst[i] = o;
}

// lora_B [4096][64] fp32 -> fp16 same layout
__global__ void cvt_lb_kernel(const float* __restrict__ lB, __half* __restrict__ lb) {
    size_t i = ((size_t)blockIdx.x * 256 + threadIdx.x) * 4;
    float4 v = *(const float4*)(lB + i);
    __half h[4] = {__float2half_rn(v.x), __float2half_rn(v.y),
                   __float2half_rn(v.z), __float2half_rn(v.w)};
    *(uint2*)&lb[i] = *(uint2*)h;
}

// lora_A [64][4096] fp32 -> lat [4096][64] fp16 (transpose)
__global__ void cvt_lat_kernel(const float* __restrict__ lA, __half* __restrict__ lat) {
    __shared__ float s[64][65];
    const int tid = threadIdx.x;
    const int i0 = blockIdx.x * 64;
    for (int idx = tid; idx < 4096; idx += 256) {
        int r = idx >> 6, ii = idx & 63;
        s[r][ii] = lA[r * IN_F + i0 + ii];
    }
    __syncthreads();
    int ii = tid >> 2, rs = (tid & 3) * 16;
    __half h[16];
#pragma unroll
    for (int j = 0; j < 16; j++) h[j] = __float2half_rn(s[rs + j][ii]);
    uint4* dst = (uint4*)&lat[(size_t)(i0 + ii) * 64 + rs];
    dst[0] = *(uint4*)&h[0];
    dst[1] = *(uint4*)&h[8];
}

// ---------------------------------------------------------------------------
// Host fallback: W_eff = NF4 dequant * absmax + lora_B @ lora_A  (fp16 out)
// ---------------------------------------------------------------------------
__global__ void build_weff_kernel(const int* __restrict__ qweight,
                                  const float* __restrict__ absmax,
                                  const float* __restrict__ lA,
                                  const float* __restrict__ lB,
                                  __half* __restrict__ dst) {
    __shared__ float Bsh[64][64];
    __shared__ float Ash[64][128];

    const int tid = threadIdx.x;
    const int o0 = blockIdx.y * 64;
    const int i0 = blockIdx.x * 128;

    for (int t = tid; t < 64 * 64; t += 256) {
        int o = t >> 6, r = t & 63;
        Bsh[r][o] = lB[(o0 + o) * 64 + r];
    }
    for (int t = tid; t < 64 * 128; t += 256) {
        int r = t >> 7, c = t & 127;
        Ash[r][c] = lA[r * IN_F + i0 + c];
    }
    __syncthreads();

    const int oo0 = (tid >> 4) * 4;
    const int ii0 = (tid & 15) * 8;

    float acc[4][8];
#pragma unroll
    for (int a = 0; a < 4; a++)
#pragma unroll
        for (int b = 0; b < 8; b++) acc[a][b] = 0.0f;

#pragma unroll 4
    for (int r = 0; r < 64; r++) {
        float4 a0 = *(const float4*)&Ash[r][ii0];
        float4 a1 = *(const float4*)&Ash[r][ii0 + 4];
#pragma unroll
        for (int oo = 0; oo < 4; oo++) {
            float bv = Bsh[r][oo0 + oo];
            acc[oo][0] += bv * a0.x; acc[oo][1] += bv * a0.y;
            acc[oo][2] += bv * a0.z; acc[oo][3] += bv * a0.w;
            acc[oo][4] += bv * a1.x; acc[oo][5] += bv * a1.y;
            acc[oo][6] += bv * a1.z; acc[oo][7] += bv * a1.w;
        }
    }

#pragma unroll
    for (int oo = 0; oo < 4; oo++) {
        const int o = o0 + oo0 + oo;
        const size_t k = (size_t)o * IN_F + i0 + ii0;
        const int4 qv = ((const int4*)qweight)[k >> 3];
        const float am = absmax[k >> 6];

        float w[8];
        w[0] = NF4[qv.x & 15];  w[1] = NF4[(qv.x >> 4) & 15];
        w[2] = NF4[qv.y & 15];  w[3] = NF4[(qv.y >> 4) & 15];
        w[4] = NF4[qv.z & 15];  w[5] = NF4[(qv.z >> 4) & 15];
        w[6] = NF4[qv.w & 15];  w[7] = NF4[(qv.w >> 4) & 15];

        __half2 h0 = __floats2half2_rn(w[0] * am + acc[oo][0], w[1] * am + acc[oo][1]);
        __half2 h1 = __floats2half2_rn(w[2] * am + acc[oo][2], w[3] * am + acc[oo][3]);
        __half2 h2 = __floats2half2_rn(w[4] * am + acc[oo][4], w[5] * am + acc[oo][5]);
        __half2 h3 = __floats2half2_rn(w[6] * am + acc[oo][6], w[7] * am + acc[oo][7]);
        uint4 pk;
        pk.x = *(uint32_t*)&h0; pk.y = *(uint32_t*)&h1;
        pk.z = *(uint32_t*)&h2; pk.w = *(uint32_t*)&h3;
        *(uint4*)&dst[k] = pk;
    }
}

// ---------------------------------------------------------------------------
// Fallback GEMM (proven 778us): fp16 mma.sync, 512 thr, 4-stage.
// ---------------------------------------------------------------------------
constexpr int BM = 128, BN = 256, BK = 64, S = 4;
constexpr int NT = IN_F / BK;
constexpr int A_BYTES = BM * 128;
constexpr int B_BYTES = BN * 128;
constexpr int STAGE = A_BYTES + B_BYTES;
constexpr int SMEM_TOTAL = 1024 + S * STAGE;
constexpr int TOTAL_TILES = (M_ROWS / BM) * (OUT_F / BN);

__device__ __forceinline__ void mma_f16(float c[4], const uint32_t a[4],
                                        uint32_t b0, uint32_t b1) {
    asm volatile(
        "mma.sync.aligned.m16n8k16.row.col.f32.f16.f16.f32 "
        "{%0,%1,%2,%3}, {%4,%5,%6,%7}, {%8,%9}, {%0,%1,%2,%3};"
        : "+f"(c[0]), "+f"(c[1]), "+f"(c[2]), "+f"(c[3])
        : "r"(a[0]), "r"(a[1]), "r"(a[2]), "r"(a[3]), "r"(b0), "r"(b1));
}

__device__ __forceinline__ void ldsm4(uint32_t& r0, uint32_t& r1,
                                      uint32_t& r2, uint32_t& r3, uint32_t addr) {
    asm volatile("ldmatrix.sync.aligned.m8n8.x4.shared.b16 {%0,%1,%2,%3}, [%4];"
                 : "=r"(r0), "=r"(r1), "=r"(r2), "=r"(r3) : "r"(addr));
}

__device__ __forceinline__ void st_cs_f2(float* p, float a, float b) {
    asm volatile("st.global.cs.v2.f32 [%0], {%1,%2};" :: "l"(p), "f"(a), "f"(b)
                 : "memory");
}

__device__ __forceinline__ void issue_stage(uint32_t sA, uint32_t sB,
                                            const __half* xb, const __half* wb,
                                            int tid) {
#pragma unroll
    for (int r = 0; r < 2; r++) {
        int i = tid + r * 512;
        int row = i >> 3, c = i & 7;
        uint32_t off = (uint32_t)(row * 128 + ((c * 16) ^ ((row & 7) << 4)));
        const __half* src = xb + (size_t)row * IN_F + c * 8;
        asm volatile("cp.async.cg.shared.global.L2::256B [%0], [%1], 16;\n"
                     :: "r"(sA + off), "l"(src));
    }
#pragma unroll
    for (int r = 0; r < 4; r++) {
        int i = tid + r * 512;
        int row = i >> 3, c = i & 7;
        uint32_t off = (uint32_t)(row * 128 + ((c * 16) ^ ((row & 7) << 4)));
        const __half* src = wb + (size_t)row * IN_F + c * 8;
        asm volatile("cp.async.cg.shared.global.L2::256B [%0], [%1], 16;\n"
                     :: "r"(sB + off), "l"(src));
    }
}

__global__ void __launch_bounds__(512, 1)
gemm_f16_kernel(const __half* __restrict__ Xh, const __half* __restrict__ Wh,
                float* __restrict__ out) {
    extern __shared__ char sm[];
    const uint32_t stage0 = (smem_u32(sm) + 1023) & ~1023u;

    const int tid = threadIdx.x;
    const int wid = tid >> 5;
    const int lane = tid & 31;
    const int warp_m = wid & 3;
    const int warp_n = wid >> 2;
    const int g = lane >> 3;
    const int r = lane & 7;

    uint32_t a_rowoff[2], a_xr[2];
    const uint32_t a_kc = (uint32_t)((g >> 1) * 16);
#pragma unroll
    for (int mf = 0; mf < 2; mf++) {
        int row = warp_m * 32 + mf * 16 + (g & 1) * 8 + r;
        a_rowoff[mf] = row * 128;
        a_xr[mf] = (row & 7) << 4;
    }
    uint32_t b_rowoff[4], b_xr[4];
    const uint32_t b_kc = (uint32_t)((g & 1) * 16);
#pragma unroll
    for (int p = 0; p < 4; p++) {
        int row = warp_n * 64 + p * 16 + (g >> 1) * 8 + r;
        b_rowoff[p] = row * 128;
        b_xr[p] = (row & 7) << 4;
    }

    for (int t = blockIdx.x; t < TOTAL_TILES; t += gridDim.x) {
        const int mBase = (t >> 4) * BM;
        const int nBase = (t & 15) * BN;
        const __half* xt = Xh + (size_t)mBase * IN_F;
        const __half* wt = Wh + (size_t)nBase * IN_F;

        float acc[2][8][4];
#pragma unroll
        for (int i = 0; i < 2; i++)
#pragma unroll
            for (int j = 0; j < 8; j++)
#pragma unroll
                for (int l = 0; l < 4; l++) acc[i][j][l] = 0.0f;

#pragma unroll
        for (int p = 0; p < S - 1; p++) {
            uint32_t sA = stage0 + p * STAGE;
            issue_stage(sA, sA + A_BYTES, xt + p * BK, wt + p * BK, tid);
            asm volatile("cp.async.commit_group;\n" ::: "memory");
        }

        for (int kt = 0; kt < NT; kt++) {
            asm volatile("cp.async.wait_group %0;\n" :: "n"(S - 2) : "memory");
            __syncthreads();

            if (kt + S - 1 < NT) {
                const int s2 = (kt + S - 1) % S;
                uint32_t sA = stage0 + s2 * STAGE;
                issue_stage(sA, sA + A_BYTES,
                            xt + (kt + S - 1) * BK, wt + (kt + S - 1) * BK, tid);
            }
            asm volatile("cp.async.commit_group;\n" ::: "memory");

            const uint32_t sA = stage0 + (kt % S) * STAGE;
            const uint32_t sB = sA + A_BYTES;

#pragma unroll
            for (int q = 0; q < 4; q++) {
                uint32_t a[2][4];
#pragma unroll
                for (int mf = 0; mf < 2; mf++)
                    ldsm4(a[mf][0], a[mf][1], a[mf][2], a[mf][3],
                          sA + a_rowoff[mf] + (((q * 32) + a_kc) ^ a_xr[mf]));
                uint32_t b[8][2];
#pragma unroll
                for (int p = 0; p < 4; p++)
                    ldsm4(b[2 * p][0], b[2 * p][1], b[2 * p + 1][0], b[2 * p + 1][1],
                          sB + b_rowoff[p] + (((q * 32) + b_kc) ^ b_xr[p]));
#pragma unroll
                for (int mf = 0; mf < 2; mf++)
#pragma unroll
                    for (int nf = 0; nf < 8; nf++)
                        mma_f16(acc[mf][nf], a[mf], b[nf][0], b[nf][1]);
            }
        }
        asm volatile("cp.async.wait_group 0;\n" ::: "memory");

#pragma unroll
        for (int mf = 0; mf < 2; mf++) {
#pragma unroll
            for (int nf = 0; nf < 8; nf++) {
                const int row = mBase + warp_m * 32 + mf * 16 + (lane >> 2);
                const int col = nBase + warp_n * 64 + nf * 8 + (lane & 3) * 2;
                st_cs_f2(&out[(size_t)row * OUT_F + col],
                         acc[mf][nf][0], acc[mf][nf][1]);
                st_cs_f2(&out[(size_t)(row + 8) * OUT_F + col],
                         acc[mf][nf][2], acc[mf][nf][3]);
            }
        }
        __syncthreads();
    }
}

// ===========================================================================
// NVRTC tcgen05 module: gemm5 (R7 proven), gemm5b (2-M-tile), wbuild (fused
// LoRA-GEMM + NF4 dequant), plus test-pattern init kernels.
// ===========================================================================
static const char* NVRTC_SRC = R"NVSRC(
typedef unsigned int u32;
typedef unsigned long long u64;
typedef unsigned short u16;

__device__ u16 GX[33554432];     // 8192*4096 fp16
__device__ u16 GW[16777216];     // 4096*4096 fp16
__device__ float GOUT[33554432]; // gemm self-test output
__device__ u16 GLB[262144];      // lora_B fp16 [4096][64]
__device__ u16 GLAT[262144];     // lora_A^T fp16 [4096][64]
__device__ int GTQW[8388608];    // wbuild self-test qweight
__device__ float GTAM[262144];   // wbuild self-test absmax

__constant__ float NF4D[16] = {
    -1.0f, -0.6961928009986877f, -0.5250730514526367f, -0.39491748809814453f,
    -0.28444138169288635f, -0.18477343022823334f, -0.09105003625154495f, 0.0f,
    0.07958029955625534f, 0.16093020141124725f, 0.24611230194568634f,
    0.33791524171829224f, 0.4407098889350891f, 0.5626170039176941f,
    0.7229568362236023f, 1.0f
};

#define MWAIT(ba, ph) do { u32 _d; \
    asm volatile("{ .reg .pred p; mbarrier.try_wait.parity.acquire.cta.shared::cta.b64 p, [%1], %2; selp.b32 %0,1,0,p; }" \
                 : "=r"(_d) : "r"(ba), "r"(ph) : "memory"); \
    if (!_d) { \
        asm volatile("{ .reg .pred P1; WL%=: mbarrier.try_wait.parity.acquire.cta.shared::cta.b64 P1, [%0], %1, 0x989680; @P1 bra.uni WD%=; bra.uni WL%=; WD%=: }" \
                     :: "r"(ba), "r"(ph) : "memory"); } } while(0)

#define LDTM32(rr, addr) \
    asm volatile("tcgen05.ld.sync.aligned.32x32b.x32.b32 " \
        "{%0,%1,%2,%3,%4,%5,%6,%7,%8,%9,%10,%11,%12,%13,%14,%15," \
        "%16,%17,%18,%19,%20,%21,%22,%23,%24,%25,%26,%27,%28,%29,%30,%31}, [%32];" \
        : "=r"(rr[0]), "=r"(rr[1]), "=r"(rr[2]), "=r"(rr[3]), \
          "=r"(rr[4]), "=r"(rr[5]), "=r"(rr[6]), "=r"(rr[7]), \
          "=r"(rr[8]), "=r"(rr[9]), "=r"(rr[10]), "=r"(rr[11]), \
          "=r"(rr[12]), "=r"(rr[13]), "=r"(rr[14]), "=r"(rr[15]), \
          "=r"(rr[16]), "=r"(rr[17]), "=r"(rr[18]), "=r"(rr[19]), \
          "=r"(rr[20]), "=r"(rr[21]), "=r"(rr[22]), "=r"(rr[23]), \
          "=r"(rr[24]), "=r"(rr[25]), "=r"(rr[26]), "=r"(rr[27]), \
          "=r"(rr[28]), "=r"(rr[29]), "=r"(rr[30]), "=r"(rr[31]) \
        : "r"(addr))

__device__ __forceinline__ u32 sm2u32(const void* p) {
    u32 a;
    asm("{ .reg .u64 t; cvta.to.shared.u64 t, %1; cvt.u32.u64 %0, t; }" : "=r"(a) : "l"(p));
    return a;
}

extern "C" __global__ void initt() {
    u64 i = (u64)blockIdx.x * 256 + threadIdx.x;
    const u16 T[9] = {0xBC00,0xBA00,0xB800,0xB400,0,0x3400,0x3800,0x3A00,0x3C00};
    if (i < 33554432ull) {
        u32 m = (u32)(i >> 12), k = (u32)(i & 4095);
        GX[i] = T[(k*131u + m*7u) % 9u];
    }
    if (i < 16777216ull) {
        u32 n = (u32)(i >> 12), k = (u32)(i & 4095);
        GW[i] = T[(k*17u + n*3u) % 7u + 1u];
    }
}

extern "C" __global__ void wtinit() {
    u64 i = (u64)blockIdx.x * 256 + threadIdx.x;
    if (i < 8388608ull) GTQW[i] = (int)((i * 37ull) & 255ull);
    if (i < 262144ull) {
        GTAM[i] = (float)((u32)(i * 13ull) % 31u + 1u) * 0.03125f;
        u32 o = (u32)(i >> 6), r = (u32)(i & 63);
        float lb = (float)((int)((o*3u + r*7u) % 17u) - 8) * 0.015625f;
        float la = (float)((int)((o*5u + r*11u) % 19u) - 9) * 0.015625f;
        u16 hb, ha;
        asm("cvt.rn.f16.f32 %0, %1;" : "=h"(hb) : "f"(lb));
        asm("cvt.rn.f16.f32 %0, %1;" : "=h"(ha) : "f"(la));
        GLB[i] = hb;
        GLAT[i] = ha;
    }
}

__device__ __forceinline__ void ld_sub(u32 dst, const char* src, int tid, int iters) {
#pragma unroll
    for (int r = 0; r < 8; r++) {
        if (r >= iters) break;
        int i = tid + r * 256; int row = i >> 3, c = i & 7;
        u32 off = (u32)(row * 128 + ((c * 16) ^ ((row & 7) << 4)));
        asm volatile("cp.async.cg.shared.global.L2::256B [%0], [%1], 16;"
                     :: "r"(dst + off), "l"(src + (u64)row * 8192 + c * 16));
    }
}

// ---------------- gemm5 (R7 proven, single M-tile) ----------------
__device__ __forceinline__ void ld_stage(u32 sA, u32 sB, const char* xb,
                                         const char* wb, int tid) {
#pragma unroll
    for (int r = 0; r < 4; r++) {
        int i = tid + r * 256; int row = i >> 3, c = i & 7;
        u32 off = (u32)(row * 128 + ((c * 16) ^ ((row & 7) << 4)));
        asm volatile("cp.async.cg.shared.global.L2::256B [%0], [%1], 16;"
                     :: "r"(sA + off), "l"(xb + (u64)row * 8192 + c * 16));
    }
#pragma unroll
    for (int r = 0; r < 8; r++) {
        int i = tid + r * 256; int row = i >> 3, c = i & 7;
        u32 off = (u32)(row * 128 + ((c * 16) ^ ((row & 7) << 4)));
        asm volatile("cp.async.cg.shared.global.L2::256B [%0], [%1], 16;"
                     :: "r"(sB + off), "l"(wb + (u64)row * 8192 + c * 16));
    }
}

extern "C" __global__ void __launch_bounds__(256, 1)
gemm5(const char* __restrict__ X, const char* __restrict__ W,
      float* __restrict__ out) {
    extern __shared__ char sm[];
    u32 base = (sm2u32(sm) + 1023) & ~1023u;
    const u32 tptr = base;
    const u32 mb = base + 16;
    const u32 st0 = base + 1024;
    const int tid = threadIdx.x, wid = tid >> 5, lid = tid & 31;

    if (wid == 0)
        asm volatile("tcgen05.alloc.cta_group::1.sync.aligned.shared::cta.b32 [%0], %1;"
                     :: "r"(tptr), "r"(256u) : "memory");
    if (tid == 0) {
#pragma unroll
        for (int s = 0; s < 4; s++)
            asm volatile("mbarrier.init.shared.b64 [%0], %1;"
                         :: "r"(mb + s * 8), "r"(1u) : "memory");
    }
    __syncthreads();
    u32 tmem; asm volatile("ld.shared.b32 %0,[%1];" : "=r"(tmem) : "r"(tptr));

    const u64 DBASE = (2ull << 61) | (1ull << 46) | (64ull << 32) | (1ull << 16);
    const u32 IDESC = (1u << 4) | (32u << 17) | (8u << 24);

#pragma unroll 1
    for (int t = blockIdx.x; t < 1024; t += gridDim.x) {
        const int mBase = (t >> 4) * 128, nBase = (t & 15) * 256;
        const char* xt = X + (u64)mBase * 8192;
        const char* wt = W + (u64)nBase * 8192;

#pragma unroll
        for (int p = 0; p < 4; p++) {
            u32 sA = st0 + p * 49152;
            ld_stage(sA, sA + 16384, xt + p * 128, wt + p * 128, tid);
            asm volatile("cp.async.commit_group;" ::: "memory");
        }

#pragma unroll 1
        for (int kt = 0; kt < 64; kt++) {
            const int s = kt & 3;
            const u32 sA = st0 + s * 49152, sB = sA + 16384;
            asm volatile("cp.async.wait_group 3;" ::: "memory");
            __syncthreads();

            if (wid == 0) {
                u32 ep;
                asm volatile("{ .reg .pred p; elect.sync _|p, 0xFFFFFFFF; selp.b32 %0,1,0,p; }"
                             : "=r"(ep));
                if (ep) {
                    asm volatile("fence.proxy.async.shared::cta;" ::: "memory");
                    u64 ad = DBASE | ((u64)(sA >> 4) & 0x3FFF);
                    u64 bd = DBASE | ((u64)(sB >> 4) & 0x3FFF);
#pragma unroll
                    for (int q = 0; q < 4; q++) {
                        u32 en = (kt > 0 || q > 0) ? 1u : 0u;
                        asm volatile("{ .reg .pred p; setp.ne.u32 p, %5, 0; "
                            "tcgen05.mma.cta_group::1.kind::f16 [%0], %1, %2, %3, {%4,%4,%4,%4}, p; }"
                            :: "r"(tmem), "l"(ad + q * 2), "l"(bd + q * 2),
                               "r"(IDESC), "r"(0u), "r"(en) : "memory");
                    }
                    asm volatile("tcgen05.commit.cta_group::1.mbarrier::arrive::one.shared::cluster.b64 [%0];"
                                 :: "r"(mb + s * 8) : "memory");
                }
            }

            if (kt + 4 < 64) {
                u32 ph = (u32)((kt >> 2) & 1);
                MWAIT(mb + s * 8, ph);
                ld_stage(sA, sB, xt + (kt + 4) * 128, wt + (kt + 4) * 128, tid);
            }
            asm volatile("cp.async.commit_group;" ::: "memory");
        }

        MWAIT(mb + 24, 1u);
        asm volatile("tcgen05.fence::after_thread_sync;" ::: "memory");

        if (wid < 4) {
            float* dst = out + (u64)(mBase + wid * 32 + lid) * 4096 + nBase;
#pragma unroll
            for (int ch = 0; ch < 8; ch++) {
                u32 rr[32];
                LDTM32(rr, tmem + ch * 32);
                asm volatile("tcgen05.wait::ld.sync.aligned;" ::: "memory");
#pragma unroll
                for (int j = 0; j < 8; j++)
                    asm volatile("st.global.cs.v4.b32 [%0], {%1,%2,%3,%4};"
                                 :: "l"(dst + ch * 32 + j * 4),
                                    "r"(rr[4 * j]), "r"(rr[4 * j + 1]),
                                    "r"(rr[4 * j + 2]), "r"(rr[4 * j + 3]) : "memory");
            }
            asm volatile("tcgen05.fence::before_thread_sync;" ::: "memory");
        }
        __syncthreads();
    }

    __syncthreads();
    if (wid == 0) {
        asm volatile("tcgen05.relinquish_alloc_permit.cta_group::1.sync.aligned;");
        asm volatile("tcgen05.dealloc.cta_group::1.sync.aligned.b32 %0, %1;"
                     :: "r"(tmem), "r"(256u));
    }
}

// ---------------- gemm5b: 2 M-tiles per CTA (super-tile 256x256) ----------------
extern "C" __global__ void __launch_bounds__(256, 1)
gemm5b(const char* __restrict__ X, const char* __restrict__ W,
       float* __restrict__ out) {
    extern __shared__ char sm[];
    u32 base = (sm2u32(sm) + 1023) & ~1023u;
    const u32 tptr = base;
    const u32 mb = base + 16;
    const u32 st0 = base + 1024;          // per stage: A0 16K | A1 16K | B 32K
    const int tid = threadIdx.x, wid = tid >> 5, lid = tid & 31;

    if (wid == 0)
        asm volatile("tcgen05.alloc.cta_group::1.sync.aligned.shared::cta.b32 [%0], %1;"
                     :: "r"(tptr), "r"(512u) : "memory");
    if (tid == 0) {
#pragma unroll
        for (int s = 0; s < 3; s++)
            asm volatile("mbarrier.init.shared.b64 [%0], %1;"
                         :: "r"(mb + s * 8), "r"(1u) : "memory");
    }
    __syncthreads();
    u32 tmem; asm volatile("ld.shared.b32 %0,[%1];" : "=r"(tmem) : "r"(tptr));

    const u64 DBASE = (2ull << 61) | (1ull << 46) | (64ull << 32) | (1ull << 16);
    const u32 IDESC = (1u << 4) | (32u << 17) | (8u << 24);  // M=128, N=256, f16

    int bp1 = 0, bp2 = 0;   // slot base parities (slot0 stays 0: 22 commits/tile)

#pragma unroll 1
    for (int t = blockIdx.x; t < 512; t += gridDim.x) {
        const int mBase = (t >> 4) * 256, nBase = (t & 15) * 256;
        const char* x0 = X + (u64)mBase * 8192;
        const char* x1 = x0 + 1048576;                // +128 rows
        const char* wt = W + (u64)nBase * 8192;

#pragma unroll
        for (int p = 0; p < 3; p++) {
            u32 sA0 = st0 + p * 65536;
            ld_sub(sA0,         x0 + p * 128, tid, 4);
            ld_sub(sA0 + 16384, x1 + p * 128, tid, 4);
            ld_sub(sA0 + 32768, wt + p * 128, tid, 8);
            asm volatile("cp.async.commit_group;" ::: "memory");
        }

#pragma unroll 1
        for (int kt = 0; kt < 64; kt++) {
            const int kdiv = kt / 3;
            const int s = kt - kdiv * 3;
            const u32 sA0 = st0 + s * 65536, sA1 = sA0 + 16384, sB = sA0 + 32768;
            asm volatile("cp.async.wait_group 2;" ::: "memory");
            __syncthreads();

            if (wid == 0) {
                u32 ep;
                asm volatile("{ .reg .pred p; elect.sync _|p, 0xFFFFFFFF; selp.b32 %0,1,0,p; }"
                             : "=r"(ep));
                if (ep) {
                    asm volatile("fence.proxy.async.shared::cta;" ::: "memory");
                    u64 a0 = DBASE | ((u64)(sA0 >> 4) & 0x3FFF);
                    u64 a1 = DBASE | ((u64)(sA1 >> 4) & 0x3FFF);
                    u64 bd = DBASE | ((u64)(sB >> 4) & 0x3FFF);
#pragma unroll
                    for (int q = 0; q < 4; q++) {
                        u32 en = (kt > 0 || q > 0) ? 1u : 0u;
                        asm volatile("{ .reg .pred p; setp.ne.u32 p, %5, 0; "
                            "tcgen05.mma.cta_group::1.kind::f16 [%0], %1, %2, %3, {%4,%4,%4,%4}, p; }"
                            :: "r"(tmem), "l"(a0 + q * 2), "l"(bd + q * 2),
                               "r"(IDESC), "r"(0u), "r"(en) : "memory");
                        asm volatile("{ .reg .pred p; setp.ne.u32 p, %5, 0; "
                            "tcgen05.mma.cta_group::1.kind::f16 [%0], %1, %2, %3, {%4,%4,%4,%4}, p; }"
                            :: "r"(tmem + 256), "l"(a1 + q * 2), "l"(bd + q * 2),
                               "r"(IDESC), "r"(0u), "r"(en) : "memory");
                    }
                    asm volatile("tcgen05.commit.cta_group::1.mbarrier::arrive::one.shared::cluster.b64 [%0];"
                                 :: "r"(mb + s * 8) : "memory");
                }
            }

            if (kt + 3 < 64) {
                int bps = (s == 0) ? 0 : ((s == 1) ? bp1 : bp2);
                u32 ph = (u32)(bps ^ (kdiv & 1));
                MWAIT(mb + s * 8, ph);
                ld_sub(sA0, x0 + (kt + 3) * 128, tid, 4);
                ld_sub(sA1, x1 + (kt + 3) * 128, tid, 4);
                ld_sub(sB,  wt + (kt + 3) * 128, tid, 8);
            }
            asm volatile("cp.async.commit_group;" ::: "memory");
        }

        // drain: kt=63 commit on slot 0 (22nd this tile; slot0 base parity 0)
        MWAIT(mb, 1u);
        asm volatile("tcgen05.fence::after_thread_sync;" ::: "memory");

        {
            const int half = wid >> 2, wr = wid & 3;
            float* dst = out + (u64)(mBase + half * 128 + wr * 32 + lid) * 4096 + nBase;
            const u32 tm = tmem + half * 256;
#pragma unroll
            for (int ch = 0; ch < 8; ch++) {
                u32 rr[32];
                LDTM32(rr, tm + ch * 32);
                asm volatile("tcgen05.wait::ld.sync.aligned;" ::: "memory");
#pragma unroll
                for (int j = 0; j < 8; j++)
                    asm volatile("st.global.cs.v4.b32 [%0], {%1,%2,%3,%4};"
                                 :: "l"(dst + ch * 32 + j * 4),
                                    "r"(rr[4 * j]), "r"(rr[4 * j + 1]),
                                    "r"(rr[4 * j + 2]), "r"(rr[4 * j + 3]) : "memory");
            }
            asm volatile("tcgen05.fence::before_thread_sync;" ::: "memory");
        }
        __syncthreads();
        bp1 ^= 1; bp2 ^= 1;   // 21 commits each on slots 1,2 per tile
    }

    __syncthreads();
    if (wid == 0) {
        asm volatile("tcgen05.relinquish_alloc_permit.cta_group::1.sync.aligned;");
        asm volatile("tcgen05.dealloc.cta_group::1.sync.aligned.b32 %0, %1;"
                     :: "r"(tmem), "r"(512u));
    }
}

// ---------------- wbuild: fused LoRA GEMM + NF4 dequant ----------------
// W[o][i] = NF4[nib]*absmax + (lora_B @ lora_A)[o][i], fp16 out.
// Per CTA: 128(o) x 256(i), K=64. A = lb rows, B = lat rows. grid 512.
extern "C" __global__ void __launch_bounds__(256, 1)
wbuild(const int* __restrict__ qw, const float* __restrict__ am,
       const u16* __restrict__ lb, const u16* __restrict__ lat,
       u16* __restrict__ w) {
    extern __shared__ char sm[];
    u32 base = (sm2u32(sm) + 1023) & ~1023u;
    const u32 tptr = base;
    const u32 mb = base + 16;
    const u32 sa = base + 1024;
    const u32 sb = sa + 16384;
    const int tid = threadIdx.x, wid = tid >> 5, lid = tid & 31;
    const int ti = blockIdx.x;
    const int o0 = (ti >> 4) * 128, i0 = (ti & 15) * 256;

    if (wid == 0)
        asm volatile("tcgen05.alloc.cta_group::1.sync.aligned.shared::cta.b32 [%0], %1;"
                     :: "r"(tptr), "r"(256u) : "memory");
    if (tid == 0)
        asm volatile("mbarrier.init.shared.b64 [%0], %1;" :: "r"(mb), "r"(1u) : "memory");
    __syncthreads();
    u32 tmem; asm volatile("ld.shared.b32 %0,[%1];" : "=r"(tmem) : "r"(tptr));

    // load tiles (rows are 64 fp16 = 128B, contiguous arrays)
#pragma unroll
    for (int r = 0; r < 4; r++) {
        int i = tid + r * 256; int row = i >> 3, c = i & 7;
        u32 off = (u32)(row * 128 + ((c * 16) ^ ((row & 7) << 4)));
        asm volatile("cp.async.cg.shared.global [%0], [%1], 16;"
                     :: "r"(sa + off), "l"((const char*)lb + (u64)(o0 + row) * 128 + c * 16));
    }
#pragma unroll
    for (int r = 0; r < 8; r++) {
        int i = tid + r * 256; int row = i >> 3, c = i & 7;
        u32 off = (u32)(row * 128 + ((c * 16) ^ ((row & 7) << 4)));
        asm volatile("cp.async.cg.shared.global [%0], [%1], 16;"
                     :: "r"(sb + off), "l"((const char*)lat + (u64)(i0 + row) * 128 + c * 16));
    }
    asm volatile("cp.async.commit_group;" ::: "memory");
    asm volatile("cp.async.wait_group 0;" ::: "memory");
    __syncthreads();

    const u64 DBASE = (2ull << 61) | (1ull << 46) | (64ull << 32) | (1ull << 16);
    const u32 IDESC = (1u << 4) | (32u << 17) | (8u << 24);

    if (wid == 0) {
        u32 ep;
        asm volatile("{ .reg .pred p; elect.sync _|p, 0xFFFFFFFF; selp.b32 %0,1,0,p; }"
                     : "=r"(ep));
        if (ep) {
            asm volatile("fence.proxy.async.shared::cta;" ::: "memory");
            u64 ad = DBASE | ((u64)(sa >> 4) & 0x3FFF);
            u64 bd = DBASE | ((u64)(sb >> 4) & 0x3FFF);
#pragma unroll
            for (int q = 0; q < 4; q++) {
                u32 en = (q > 0) ? 1u : 0u;
                asm volatile("{ .reg .pred p; setp.ne.u32 p, %5, 0; "
                    "tcgen05.mma.cta_group::1.kind::f16 [%0], %1, %2, %3, {%4,%4,%4,%4}, p; }"
                    :: "r"(tmem), "l"(ad + q * 2), "l"(bd + q * 2),
                       "r"(IDESC), "r"(0u), "r"(en) : "memory");
            }
            asm volatile("tcgen05.commit.cta_group::1.mbarrier::arrive::one.shared::cluster.b64 [%0];"
                         :: "r"(mb) : "memory");
        }
    }
    __syncthreads();
    MWAIT(mb, 0u);
    asm volatile("tcgen05.fence::after_thread_sync;" ::: "memory");

    const int half = wid >> 2, wr = wid & 3;
    const int o = o0 + wr * 32 + lid;
#pragma unroll
    for (int c4 = 0; c4 < 4; c4++) {
        u32 rr[32];
        LDTM32(rr, tmem + half * 128 + c4 * 32);
        asm volatile("tcgen05.wait::ld.sync.aligned;" ::: "memory");
        const u64 k = (u64)o * 4096 + (u64)(i0 + half * 128 + c4 * 32);
        const float a = am[k >> 6];
        const int4* qp = (const int4*)qw + (k >> 3);
        u32 ov[16];
#pragma unroll
        for (int u = 0; u < 4; u++) {
            int4 qv = qp[u];
            int e[8] = {qv.x & 15, (qv.x >> 4) & 15, qv.y & 15, (qv.y >> 4) & 15,
                        qv.z & 15, (qv.z >> 4) & 15, qv.w & 15, (qv.w >> 4) & 15};
#pragma unroll
            for (int j = 0; j < 4; j++) {
                union { u32 u_; float f_; } c0, c1;
                c0.u_ = rr[u * 8 + 2 * j];
                c1.u_ = rr[u * 8 + 2 * j + 1];
                float w0 = NF4D[e[2 * j]] * a + c0.f_;
                float w1 = NF4D[e[2 * j + 1]] * a + c1.f_;
                asm("cvt.rn.f16x2.f32 %0, %1, %2;" : "=r"(ov[u * 4 + j]) : "f"(w1), "f"(w0));
            }
        }
        char* wp = (char*)w + k * 2;
#pragma unroll
        for (int j = 0; j < 4; j++)
            asm volatile("st.global.cs.v4.b32 [%0], {%1,%2,%3,%4};"
                         :: "l"(wp + j * 16), "r"(ov[4 * j]), "r"(ov[4 * j + 1]),
                            "r"(ov[4 * j + 2]), "r"(ov[4 * j + 3]) : "memory");
    }
    asm volatile("tcgen05.fence::before_thread_sync;" ::: "memory");
    __syncthreads();
    if (wid == 0) {
        asm volatile("tcgen05.relinquish_alloc_permit.cta_group::1.sync.aligned;");
        asm volatile("tcgen05.dealloc.cta_group::1.sync.aligned.b32 %0, %1;"
                     :: "r"(tmem), "r"(256u));
    }
}
)NVSRC";

// --- driver/nvrtc plumbing ---
typedef int (*nvrtcCreateProgram_t)(void**, const char*, const char*, int,
                                    const char* const*, const char* const*);
typedef int (*nvrtcCompileProgram_t)(void*, int, const char* const*);
typedef int (*nvrtcGetCUBINSize_t)(void*, size_t*);
typedef int (*nvrtcGetCUBIN_t)(void*, char*);
typedef int (*cuInit_t)(unsigned);
typedef int (*cuDevicePrimaryCtxRetain_t)(void**, int);
typedef int (*cuCtxSetCurrent_t)(void*);
typedef int (*cuModuleLoadDataEx_t)(void**, const void*, unsigned, int*, void**);
typedef int (*cuModuleGetFunction_t)(void**, void*, const char*);
typedef int (*cuModuleGetGlobal_t)(unsigned long long*, size_t*, void*, const char*);
typedef int (*cuFuncSetAttribute_t)(void*, int, int);
typedef int (*cuLaunchKernel_t)(void*, unsigned, unsigned, unsigned,
                                unsigned, unsigned, unsigned,
                                unsigned, void*, void**, void**);
typedef int (*cuCtxSynchronize_t)(void);
typedef int (*cuMemcpyDtoH_t)(void*, unsigned long long, size_t);

#if defined(CUDA_API_PER_THREAD_DEFAULT_STREAM) || defined(__CUDA_API_PER_THREAD_DEFAULT_STREAM)
#define DRV_STREAM ((void*)0x2)
#else
#define DRV_STREAM ((void*)0x1)
#endif

static bool g_ok_gemm = false, g_ok_wb = false;
static cuLaunchKernel_t p_cuLaunchKernel = nullptr;
static void* g_fn_gemm = nullptr;
static void* g_fn_wbuild = nullptr;
static unsigned long long g_gx = 0, g_gw = 0, g_glb = 0, g_glat = 0;
constexpr int SMEM5 = 198656;
constexpr int SMEMW = 51200;

static float h2f(uint16_t h) {
    uint32_t s = (h >> 15) & 1, e = (h >> 10) & 31, m = h & 1023;
    uint32_t f;
    if (e == 0) {
        if (m == 0) f = s << 31;
        else {
            e = 127 - 15 + 1;
            while (!(m & 1024)) { m <<= 1; e--; }
            m &= 1023;
            f = (s << 31) | (e << 23) | (m << 13);
        }
    } else if (e == 31) f = (s << 31) | 0x7F800000 | (m << 13);
    else f = (s << 31) | ((e - 15 + 127) << 23) | (m << 13);
    float r; memcpy(&r, &f, 4); return r;
}

static bool try_init_tcgen05() {
    void* hcu = dlopen("libcuda.so.1", RTLD_NOW | RTLD_GLOBAL);
    if (!hcu) hcu = dlopen("libcuda.so", RTLD_NOW | RTLD_GLOBAL);
    if (!hcu) return false;
    void* hnv = dlopen("libnvrtc.so.13", RTLD_NOW | RTLD_GLOBAL);
    if (!hnv) hnv = dlopen("libnvrtc.so", RTLD_NOW | RTLD_GLOBAL);
    if (!hnv) hnv = dlopen("libnvrtc.so.12", RTLD_NOW | RTLD_GLOBAL);
    if (!hnv) return false;

    auto nCreate  = (nvrtcCreateProgram_t)dlsym(hnv, "nvrtcCreateProgram");
    auto nCompile = (nvrtcCompileProgram_t)dlsym(hnv, "nvrtcCompileProgram");
    auto nCbSize  = (nvrtcGetCUBINSize_t)dlsym(hnv, "nvrtcGetCUBINSize");
    auto nCb      = (nvrtcGetCUBIN_t)dlsym(hnv, "nvrtcGetCUBIN");
    auto cInit    = (cuInit_t)dlsym(hcu, "cuInit");
    auto cRetain  = (cuDevicePrimaryCtxRetain_t)dlsym(hcu, "cuDevicePrimaryCtxRetain");
    auto cSetCur  = (cuCtxSetCurrent_t)dlsym(hcu, "cuCtxSetCurrent");
    auto cModLoad = (cuModuleLoadDataEx_t)dlsym(hcu, "cuModuleLoadDataEx");
    auto cGetFn   = (cuModuleGetFunction_t)dlsym(hcu, "cuModuleGetFunction");
    auto cGetGlb  = (cuModuleGetGlobal_t)dlsym(hcu, "cuModuleGetGlobal_v2");
    auto cSetAttr = (cuFuncSetAttribute_t)dlsym(hcu, "cuFuncSetAttribute");
    auto cLaunch  = (cuLaunchKernel_t)dlsym(hcu, "cuLaunchKernel");
    auto cSync    = (cuCtxSynchronize_t)dlsym(hcu, "cuCtxSynchronize");
    auto cD2H     = (cuMemcpyDtoH_t)dlsym(hcu, "cuMemcpyDtoH_v2");
    if (!nCreate || !nCompile || !nCbSize || !nCb || !cInit || !cRetain ||
        !cSetCur || !cModLoad || !cGetFn || !cGetGlb || !cSetAttr ||
        !cLaunch || !cSync || !cD2H)
        return false;

    if (cInit(0)) return false;
    void* ctx = nullptr;
    if (cRetain(&ctx, 0)) return false;
    if (cSetCur(ctx)) return false;

    void* prog = nullptr;
    if (nCreate(&prog, NVRTC_SRC, "gemm5.cu", 0, nullptr, nullptr)) return false;
    const char* opts[] = {"--gpu-architecture=sm_103a"};
    if (nCompile(prog, 1, opts)) return false;
    size_t cbsz = 0;
    if (nCbSize(prog, &cbsz) || cbsz == 0) return false;
    static char* cubin = new char[cbsz];
    if (nCb(prog, cubin)) return false;

    void* mod = nullptr;
    if (cModLoad(&mod, cubin, 0, nullptr, nullptr)) return false;
    void *fG5 = nullptr, *fG5b = nullptr, *fInit = nullptr, *fWb = nullptr, *fWti = nullptr;
    if (cGetFn(&fG5, mod, "gemm5")) return false;
    if (cGetFn(&fG5b, mod, "gemm5b")) return false;
    if (cGetFn(&fInit, mod, "initt")) return false;
    if (cGetFn(&fWb, mod, "wbuild")) return false;
    if (cGetFn(&fWti, mod, "wtinit")) return false;
    unsigned long long gx = 0, gw = 0, gout = 0, glb = 0, glat = 0, gtqw = 0, gtam = 0;
    size_t sz;
    if (cGetGlb(&gx, &sz, mod, "GX")) return false;
    if (cGetGlb(&gw, &sz, mod, "GW")) return false;
    if (cGetGlb(&gout, &sz, mod, "GOUT")) return false;
    if (cGetGlb(&glb, &sz, mod, "GLB")) return false;
    if (cGetGlb(&glat, &sz, mod, "GLAT")) return false;
    if (cGetGlb(&gtqw, &sz, mod, "GTQW")) return false;
    if (cGetGlb(&gtam, &sz, mod, "GTAM")) return false;
    if (cSetAttr(fG5, 8, SMEM5)) return false;
    if (cSetAttr(fG5b, 8, SMEM5)) return false;
    if (cSetAttr(fWb, 8, SMEMW)) return false;

    p_cuLaunchKernel = cLaunch;
    g_gx = gx; g_gw = gw; g_glb = glb; g_glat = glat;

    // ---- gemm self-test (exact integer grid) ----
    if (cLaunch(fInit, 131072, 1, 1, 256, 1, 1, 0, DRV_STREAM, nullptr, nullptr))
        return false;
    static float row[OUT_F];
    const int ms[4] = {0, 97, 4095, 8191};
    auto test_gemm = [&](void* fn) -> bool {
        unsigned long long px = gx, pw = gw, po = gout;
        void* args[3] = {&px, &pw, &po};
        if (cLaunch(fn, 148, 1, 1, 256, 1, 1, SMEM5, DRV_STREAM, args, nullptr))
            return false;
        if (cSync()) return false;
        for (int ri = 0; ri < 4; ri++) {
            int m = ms[ri];
            if (cD2H(row, gout + (unsigned long long)m * OUT_F * 4, OUT_F * 4))
                return false;
            for (int n = 0; n < OUT_F; n++) {
                float ref = 0.0f;
                for (int k = 0; k < IN_F; k++) {
                    int av = (k * 131 + m * 7) % 9 - 4;
                    int bv = (k * 17 + n * 3) % 7 - 3;
                    ref += (av * 0.25f) * (bv * 0.25f);
                }
                if (fabsf(row[n] - ref) > 0.01f) return false;
            }
        }
        return true;
    };
    if (test_gemm(fG5b)) { g_fn_gemm = fG5b; g_ok_gemm = true; }
    else if (test_gemm(fG5)) { g_fn_gemm = fG5; g_ok_gemm = true; }
    if (!g_ok_gemm) return false;

    // ---- wbuild self-test ----
    do {
        if (cLaunch(fWti, 32768, 1, 1, 256, 1, 1, 0, DRV_STREAM, nullptr, nullptr))
            break;
        unsigned long long pq = gtqw, pa = gtam, pl = glb, pt = glat, pw2 = gw;
        void* args[5] = {&pq, &pa, &pl, &pt, &pw2};
        if (cLaunch(fWb, 512, 1, 1, 256, 1, 1, SMEMW, DRV_STREAM, args, nullptr))
            break;
        if (cSync()) break;
        static uint16_t wrow[IN_F];
        const int os[4] = {0, 1, 255, 4095};
        bool ok = true;
        for (int oi = 0; oi < 4 && ok; oi++) {
            int o = os[oi];
            if (cD2H(wrow, gw + (unsigned long long)o * IN_F * 2, IN_F * 2)) { ok = false; break; }
            for (int i = 0; i < IN_F; i++) {
                uint64_t k = (uint64_t)o * 4096 + i;
                uint64_t t = k >> 1;
                int qv = (int)((t * 37ull) & 255ull);
                int nib = (k & 1) ? (qv >> 4) & 15 : qv & 15;
                float a = (float)(((uint32_t)((k >> 6) * 13ull)) % 31u + 1u) * 0.03125f;
                float lora = 0.0f;
                for (int r = 0; r < 64; r++) {
                    float lb = (float)((int)(((uint32_t)o * 3u + r * 7u) % 17u) - 8) * 0.015625f;
                    float la = (float)((int)(((uint32_t)i * 5u + r * 11u) % 19u) - 9) * 0.015625f;
                    lora += lb * la;
                }
                float ref = NF4H[nib] * a + lora;
                if (fabsf(h2f(wrow[i]) - ref) > 0.01f) { ok = false; break; }
            }
        }
        if (ok) { g_fn_wbuild = fWb; g_ok_wb = true; }
    } while (0);

    return true;
}

__attribute__((constructor))
static void _init_drv() {
    try_init_tcgen05();
}

// ---------------------------------------------------------------------------
extern "C" void kernel_launch(void* const* d_in, const int* in_sizes, int n_in,
                              void* d_out, int out_size) {
    const float* x  = (const float*)d_in[0];
    const int*   qw = (const int*)d_in[1];
    const float* am = (const float*)d_in[2];
    const float* lA = (const float*)d_in[3];
    const float* lB = (const float*)d_in[4];
    float*       out = (float*)d_out;

    (void)in_sizes; (void)n_in; (void)out_size;

    if (g_ok_gemm) {
        __half* xh = (__half*)(uintptr_t)g_gx;
        __half* wh = (__half*)(uintptr_t)g_gw;

        convert_x_kernel<<<(M_ROWS * IN_F / 8) / 256, 256>>>(x, xh);

        if (g_ok_wb) {
            cvt_lb_kernel<<<256, 256>>>(lB, (__half*)(uintptr_t)g_glb);
            cvt_lat_kernel<<<64, 256>>>(lA, (__half*)(uintptr_t)g_glat);
            unsigned long long pq = (unsigned long long)(uintptr_t)qw;
            unsigned long long pa = (unsigned long long)(uintptr_t)am;
            unsigned long long pl = g_glb, pt = g_glat, pw = g_gw;
            void* args[5] = {&pq, &pa, &pl, &pt, &pw};
            p_cuLaunchKernel(g_fn_wbuild, 512, 1, 1, 256, 1, 1, SMEMW,
                             DRV_STREAM, args, nullptr);
        } else {
            build_weff_kernel<<<dim3(IN_F / 128, OUT_F / 64), 256>>>(qw, am, lA, lB, wh);
        }

        unsigned long long px = g_gx, pw2 = g_gw;
        void* po = (void*)out;
        void* args[3] = {&px, &pw2, &po};
        p_cuLaunchKernel(g_fn_gemm, 148, 1, 1, 256, 1, 1, SMEM5,
                         DRV_STREAM, args, nullptr);
    } else {
        __half* xh; __half* wh;
        cudaGetSymbolAddress((void**)&xh, g_Xh);
        cudaGetSymbolAddress((void**)&wh, g_Wh);
        convert_x_kernel<<<(M_ROWS * IN_F / 8) / 256, 256>>>(x, xh);
        build_weff_kernel<<<dim3(IN_F / 128, OUT_F / 64), 256>>>(qw, am, lA, lB, wh);
        cudaFuncSetAttribute(gemm_f16_kernel,
                             cudaFuncAttributeMaxDynamicSharedMemorySize, SMEM_TOTAL);
        gemm_f16_kernel<<<148, 512, SMEM_TOTAL>>>(xh, wh, out);
    }
}

// round 9
// speedup vs baseline: 2.2571x; 1.1954x over previous
#include <cuda_runtime.h>
#include <cuda_fp16.h>
#include <cstdint>
#include <cstdio>
#include <cstring>
#include <cmath>
#include <dlfcn.h>

#define IN_F   4096
#define OUT_F  4096
#define M_ROWS 8192

// Host-module fp16 scratch (used by the fallback path).
__device__ __half g_Xh[(size_t)M_ROWS * IN_F];
__device__ __half g_Wh[(size_t)OUT_F * IN_F];

__constant__ float NF4[16] = {
    -1.0f, -0.6961928009986877f, -0.5250730514526367f, -0.39491748809814453f,
    -0.28444138169288635f, -0.18477343022823334f, -0.09105003625154495f, 0.0f,
    0.07958029955625534f, 0.16093020141124725f, 0.24611230194568634f,
    0.33791524171829224f, 0.4407098889350891f, 0.5626170039176941f,
    0.7229568362236023f, 1.0f
};

static const float NF4H[16] = {
    -1.0f, -0.6961928009986877f, -0.5250730514526367f, -0.39491748809814453f,
    -0.28444138169288635f, -0.18477343022823334f, -0.09105003625154495f, 0.0f,
    0.07958029955625534f, 0.16093020141124725f, 0.24611230194568634f,
    0.33791524171829224f, 0.4407098889350891f, 0.5626170039176941f,
    0.7229568362236023f, 1.0f
};

__device__ __forceinline__ uint32_t smem_u32(const void* p) {
    uint32_t a;
    asm("{ .reg .u64 t; cvta.to.shared.u64 t, %1; cvt.u32.u64 %0, t; }" : "=r"(a) : "l"(p));
    return a;
}

// ---------------------------------------------------------------------------
// Kernel A: convert x (fp32) -> dst (fp16). 8 elems/thread.
// ---------------------------------------------------------------------------
__global__ void convert_x_kernel(const float* __restrict__ x, __half* __restrict__ dst) {
    size_t i = ((size_t)blockIdx.x * 256 + threadIdx.x) * 8;
    float4 v0 = *(const float4*)(x + i);
    float4 v1 = *(const float4*)(x + i + 4);
    __half2 h0 = __floats2half2_rn(v0.x, v0.y);
    __half2 h1 = __floats2half2_rn(v0.z, v0.w);
    __half2 h2 = __floats2half2_rn(v1.x, v1.y);
    __half2 h3 = __floats2half2_rn(v1.z, v1.w);
    uint4 o;
    o.x = *(uint32_t*)&h0; o.y = *(uint32_t*)&h1;
    o.z = *(uint32_t*)&h2; o.w = *(uint32_t*)&h3;
    *(uint4*)&dst[i] = o;
}

// lora_B [4096][64] fp32 -> fp16 same layout
__global__ void cvt_lb_kernel(const float* __restrict__ lB, __half* __restrict__ lb) {
    size_t i = ((size_t)blockIdx.x * 256 + threadIdx.x) * 4;
    float4 v = *(const float4*)(lB + i);
    __half h[4] = {__float2half_rn(v.x), __float2half_rn(v.y),
                   __float2half_rn(v.z), __float2half_rn(v.w)};
    *(uint2*)&lb[i] = *(uint2*)h;
}

// lora_A [64][4096] fp32 -> lat [4096][64] fp16 (transpose)
__global__ void cvt_lat_kernel(const float* __restrict__ lA, __half* __restrict__ lat) {
    __shared__ float s[64][65];
    const int tid = threadIdx.x;
    const int i0 = blockIdx.x * 64;
    for (int idx = tid; idx < 4096; idx += 256) {
        int r = idx >> 6, ii = idx & 63;
        s[r][ii] = lA[r * IN_F + i0 + ii];
    }
    __syncthreads();
    int ii = tid >> 2, rs = (tid & 3) * 16;
    __half h[16];
#pragma unroll
    for (int j = 0; j < 16; j++) h[j] = __float2half_rn(s[rs + j][ii]);
    uint4* dst = (uint4*)&lat[(size_t)(i0 + ii) * 64 + rs];
    dst[0] = *(uint4*)&h[0];
    dst[1] = *(uint4*)&h[8];
}

// ---------------------------------------------------------------------------
// Host fallback: W_eff = NF4 dequant * absmax + lora_B @ lora_A  (fp16 out)
// ---------------------------------------------------------------------------
__global__ void build_weff_kernel(const int* __restrict__ qweight,
                                  const float* __restrict__ absmax,
                                  const float* __restrict__ lA,
                                  const float* __restrict__ lB,
                                  __half* __restrict__ dst) {
    __shared__ float Bsh[64][64];
    __shared__ float Ash[64][128];

    const int tid = threadIdx.x;
    const int o0 = blockIdx.y * 64;
    const int i0 = blockIdx.x * 128;

    for (int t = tid; t < 64 * 64; t += 256) {
        int o = t >> 6, r = t & 63;
        Bsh[r][o] = lB[(o0 + o) * 64 + r];
    }
    for (int t = tid; t < 64 * 128; t += 256) {
        int r = t >> 7, c = t & 127;
        Ash[r][c] = lA[r * IN_F + i0 + c];
    }
    __syncthreads();

    const int oo0 = (tid >> 4) * 4;
    const int ii0 = (tid & 15) * 8;

    float acc[4][8];
#pragma unroll
    for (int a = 0; a < 4; a++)
#pragma unroll
        for (int b = 0; b < 8; b++) acc[a][b] = 0.0f;

#pragma unroll 4
    for (int r = 0; r < 64; r++) {
        float4 a0 = *(const float4*)&Ash[r][ii0];
        float4 a1 = *(const float4*)&Ash[r][ii0 + 4];
#pragma unroll
        for (int oo = 0; oo < 4; oo++) {
            float bv = Bsh[r][oo0 + oo];
            acc[oo][0] += bv * a0.x; acc[oo][1] += bv * a0.y;
            acc[oo][2] += bv * a0.z; acc[oo][3] += bv * a0.w;
            acc[oo][4] += bv * a1.x; acc[oo][5] += bv * a1.y;
            acc[oo][6] += bv * a1.z; acc[oo][7] += bv * a1.w;
        }
    }

#pragma unroll
    for (int oo = 0; oo < 4; oo++) {
        const int o = o0 + oo0 + oo;
        const size_t k = (size_t)o * IN_F + i0 + ii0;
        const int4 qv = ((const int4*)qweight)[k >> 3];
        const float am = absmax[k >> 6];

        float w[8];
        w[0] = NF4[qv.x & 15];  w[1] = NF4[(qv.x >> 4) & 15];
        w[2] = NF4[qv.y & 15];  w[3] = NF4[(qv.y >> 4) & 15];
        w[4] = NF4[qv.z & 15];  w[5] = NF4[(qv.z >> 4) & 15];
        w[6] = NF4[qv.w & 15];  w[7] = NF4[(qv.w >> 4) & 15];

        __half2 h0 = __floats2half2_rn(w[0] * am + acc[oo][0], w[1] * am + acc[oo][1]);
        __half2 h1 = __floats2half2_rn(w[2] * am + acc[oo][2], w[3] * am + acc[oo][3]);
        __half2 h2 = __floats2half2_rn(w[4] * am + acc[oo][4], w[5] * am + acc[oo][5]);
        __half2 h3 = __floats2half2_rn(w[6] * am + acc[oo][6], w[7] * am + acc[oo][7]);
        uint4 pk;
        pk.x = *(uint32_t*)&h0; pk.y = *(uint32_t*)&h1;
        pk.z = *(uint32_t*)&h2; pk.w = *(uint32_t*)&h3;
        *(uint4*)&dst[k] = pk;
    }
}

// ---------------------------------------------------------------------------
// Fallback GEMM (proven 778us): fp16 mma.sync, 512 thr, 4-stage.
// ---------------------------------------------------------------------------
constexpr int BM = 128, BN = 256, BK = 64, S = 4;
constexpr int NT = IN_F / BK;
constexpr int A_BYTES = BM * 128;
constexpr int B_BYTES = BN * 128;
constexpr int STAGE = A_BYTES + B_BYTES;
constexpr int SMEM_TOTAL = 1024 + S * STAGE;
constexpr int TOTAL_TILES = (M_ROWS / BM) * (OUT_F / BN);

__device__ __forceinline__ void mma_f16(float c[4], const uint32_t a[4],
                                        uint32_t b0, uint32_t b1) {
    asm volatile(
        "mma.sync.aligned.m16n8k16.row.col.f32.f16.f16.f32 "
        "{%0,%1,%2,%3}, {%4,%5,%6,%7}, {%8,%9}, {%0,%1,%2,%3};"
        : "+f"(c[0]), "+f"(c[1]), "+f"(c[2]), "+f"(c[3])
        : "r"(a[0]), "r"(a[1]), "r"(a[2]), "r"(a[3]), "r"(b0), "r"(b1));
}

__device__ __forceinline__ void ldsm4(uint32_t& r0, uint32_t& r1,
                                      uint32_t& r2, uint32_t& r3, uint32_t addr) {
    asm volatile("ldmatrix.sync.aligned.m8n8.x4.shared.b16 {%0,%1,%2,%3}, [%4];"
                 : "=r"(r0), "=r"(r1), "=r"(r2), "=r"(r3) : "r"(addr));
}

__device__ __forceinline__ void st_cs_f2(float* p, float a, float b) {
    asm volatile("st.global.cs.v2.f32 [%0], {%1,%2};" :: "l"(p), "f"(a), "f"(b)
                 : "memory");
}

__device__ __forceinline__ void issue_stage(uint32_t sA, uint32_t sB,
                                            const __half* xb, const __half* wb,
                                            int tid) {
#pragma unroll
    for (int r = 0; r < 2; r++) {
        int i = tid + r * 512;
        int row = i >> 3, c = i & 7;
        uint32_t off = (uint32_t)(row * 128 + ((c * 16) ^ ((row & 7) << 4)));
        const __half* src = xb + (size_t)row * IN_F + c * 8;
        asm volatile("cp.async.cg.shared.global.L2::256B [%0], [%1], 16;\n"
                     :: "r"(sA + off), "l"(src));
    }
#pragma unroll
    for (int r = 0; r < 4; r++) {
        int i = tid + r * 512;
        int row = i >> 3, c = i & 7;
        uint32_t off = (uint32_t)(row * 128 + ((c * 16) ^ ((row & 7) << 4)));
        const __half* src = wb + (size_t)row * IN_F + c * 8;
        asm volatile("cp.async.cg.shared.global.L2::256B [%0], [%1], 16;\n"
                     :: "r"(sB + off), "l"(src));
    }
}

__global__ void __launch_bounds__(512, 1)
gemm_f16_kernel(const __half* __restrict__ Xh, const __half* __restrict__ Wh,
                float* __restrict__ out) {
    extern __shared__ char sm[];
    const uint32_t stage0 = (smem_u32(sm) + 1023) & ~1023u;

    const int tid = threadIdx.x;
    const int wid = tid >> 5;
    const int lane = tid & 31;
    const int warp_m = wid & 3;
    const int warp_n = wid >> 2;
    const int g = lane >> 3;
    const int r = lane & 7;

    uint32_t a_rowoff[2], a_xr[2];
    const uint32_t a_kc = (uint32_t)((g >> 1) * 16);
#pragma unroll
    for (int mf = 0; mf < 2; mf++) {
        int row = warp_m * 32 + mf * 16 + (g & 1) * 8 + r;
        a_rowoff[mf] = row * 128;
        a_xr[mf] = (row & 7) << 4;
    }
    uint32_t b_rowoff[4], b_xr[4];
    const uint32_t b_kc = (uint32_t)((g & 1) * 16);
#pragma unroll
    for (int p = 0; p < 4; p++) {
        int row = warp_n * 64 + p * 16 + (g >> 1) * 8 + r;
        b_rowoff[p] = row * 128;
        b_xr[p] = (row & 7) << 4;
    }

    for (int t = blockIdx.x; t < TOTAL_TILES; t += gridDim.x) {
        const int mBase = (t >> 4) * BM;
        const int nBase = (t & 15) * BN;
        const __half* xt = Xh + (size_t)mBase * IN_F;
        const __half* wt = Wh + (size_t)nBase * IN_F;

        float acc[2][8][4];
#pragma unroll
        for (int i = 0; i < 2; i++)
#pragma unroll
            for (int j = 0; j < 8; j++)
#pragma unroll
                for (int l = 0; l < 4; l++) acc[i][j][l] = 0.0f;

#pragma unroll
        for (int p = 0; p < S - 1; p++) {
            uint32_t sA = stage0 + p * STAGE;
            issue_stage(sA, sA + A_BYTES, xt + p * BK, wt + p * BK, tid);
            asm volatile("cp.async.commit_group;\n" ::: "memory");
        }

        for (int kt = 0; kt < NT; kt++) {
            asm volatile("cp.async.wait_group %0;\n" :: "n"(S - 2) : "memory");
            __syncthreads();

            if (kt + S - 1 < NT) {
                const int s2 = (kt + S - 1) % S;
                uint32_t sA = stage0 + s2 * STAGE;
                issue_stage(sA, sA + A_BYTES,
                            xt + (kt + S - 1) * BK, wt + (kt + S - 1) * BK, tid);
            }
            asm volatile("cp.async.commit_group;\n" ::: "memory");

            const uint32_t sA = stage0 + (kt % S) * STAGE;
            const uint32_t sB = sA + A_BYTES;

#pragma unroll
            for (int q = 0; q < 4; q++) {
                uint32_t a[2][4];
#pragma unroll
                for (int mf = 0; mf < 2; mf++)
                    ldsm4(a[mf][0], a[mf][1], a[mf][2], a[mf][3],
                          sA + a_rowoff[mf] + (((q * 32) + a_kc) ^ a_xr[mf]));
                uint32_t b[8][2];
#pragma unroll
                for (int p = 0; p < 4; p++)
                    ldsm4(b[2 * p][0], b[2 * p][1], b[2 * p + 1][0], b[2 * p + 1][1],
                          sB + b_rowoff[p] + (((q * 32) + b_kc) ^ b_xr[p]));
#pragma unroll
                for (int mf = 0; mf < 2; mf++)
#pragma unroll
                    for (int nf = 0; nf < 8; nf++)
                        mma_f16(acc[mf][nf], a[mf], b[nf][0], b[nf][1]);
            }
        }
        asm volatile("cp.async.wait_group 0;\n" ::: "memory");

#pragma unroll
        for (int mf = 0; mf < 2; mf++) {
#pragma unroll
            for (int nf = 0; nf < 8; nf++) {
                const int row = mBase + warp_m * 32 + mf * 16 + (lane >> 2);
                const int col = nBase + warp_n * 64 + nf * 8 + (lane & 3) * 2;
                st_cs_f2(&out[(size_t)row * OUT_F + col],
                         acc[mf][nf][0], acc[mf][nf][1]);
                st_cs_f2(&out[(size_t)(row + 8) * OUT_F + col],
                         acc[mf][nf][2], acc[mf][nf][3]);
            }
        }
        __syncthreads();
    }
}

// ===========================================================================
// NVRTC tcgen05 module: gemm5, gemm5b, gemm5c (decoupled pipeline), wbuild.
// ===========================================================================
static const char* NVRTC_SRC = R"NVSRC(
typedef unsigned int u32;
typedef unsigned long long u64;
typedef unsigned short u16;

__device__ u16 GX[33554432];     // 8192*4096 fp16
__device__ u16 GW[16777216];     // 4096*4096 fp16
__device__ float GOUT[33554432]; // gemm self-test output
__device__ u16 GLB[262144];      // lora_B fp16 [4096][64]
__device__ u16 GLAT[262144];     // lora_A^T fp16 [4096][64]
__device__ int GTQW[8388608];    // wbuild self-test qweight
__device__ float GTAM[262144];   // wbuild self-test absmax

__constant__ float NF4D[16] = {
    -1.0f, -0.6961928009986877f, -0.5250730514526367f, -0.39491748809814453f,
    -0.28444138169288635f, -0.18477343022823334f, -0.09105003625154495f, 0.0f,
    0.07958029955625534f, 0.16093020141124725f, 0.24611230194568634f,
    0.33791524171829224f, 0.4407098889350891f, 0.5626170039176941f,
    0.7229568362236023f, 1.0f
};

#define MWAIT(ba, ph) do { u32 _d; \
    asm volatile("{ .reg .pred p; mbarrier.try_wait.parity.acquire.cta.shared::cta.b64 p, [%1], %2; selp.b32 %0,1,0,p; }" \
                 : "=r"(_d) : "r"(ba), "r"(ph) : "memory"); \
    if (!_d) { \
        asm volatile("{ .reg .pred P1; WL%=: mbarrier.try_wait.parity.acquire.cta.shared::cta.b64 P1, [%0], %1, 0x989680; @P1 bra.uni WD%=; bra.uni WL%=; WD%=: }" \
                     :: "r"(ba), "r"(ph) : "memory"); } } while(0)

#define LDTM32(rr, addr) \
    asm volatile("tcgen05.ld.sync.aligned.32x32b.x32.b32 " \
        "{%0,%1,%2,%3,%4,%5,%6,%7,%8,%9,%10,%11,%12,%13,%14,%15," \
        "%16,%17,%18,%19,%20,%21,%22,%23,%24,%25,%26,%27,%28,%29,%30,%31}, [%32];" \
        : "=r"(rr[0]), "=r"(rr[1]), "=r"(rr[2]), "=r"(rr[3]), \
          "=r"(rr[4]), "=r"(rr[5]), "=r"(rr[6]), "=r"(rr[7]), \
          "=r"(rr[8]), "=r"(rr[9]), "=r"(rr[10]), "=r"(rr[11]), \
          "=r"(rr[12]), "=r"(rr[13]), "=r"(rr[14]), "=r"(rr[15]), \
          "=r"(rr[16]), "=r"(rr[17]), "=r"(rr[18]), "=r"(rr[19]), \
          "=r"(rr[20]), "=r"(rr[21]), "=r"(rr[22]), "=r"(rr[23]), \
          "=r"(rr[24]), "=r"(rr[25]), "=r"(rr[26]), "=r"(rr[27]), \
          "=r"(rr[28]), "=r"(rr[29]), "=r"(rr[30]), "=r"(rr[31]) \
        : "r"(addr))

__device__ __forceinline__ u32 sm2u32(const void* p) {
    u32 a;
    asm("{ .reg .u64 t; cvta.to.shared.u64 t, %1; cvt.u32.u64 %0, t; }" : "=r"(a) : "l"(p));
    return a;
}

extern "C" __global__ void initt() {
    u64 i = (u64)blockIdx.x * 256 + threadIdx.x;
    const u16 T[9] = {0xBC00,0xBA00,0xB800,0xB400,0,0x3400,0x3800,0x3A00,0x3C00};
    if (i < 33554432ull) {
        u32 m = (u32)(i >> 12), k = (u32)(i & 4095);
        GX[i] = T[(k*131u + m*7u) % 9u];
    }
    if (i < 16777216ull) {
        u32 n = (u32)(i >> 12), k = (u32)(i & 4095);
        GW[i] = T[(k*17u + n*3u) % 7u + 1u];
    }
}

extern "C" __global__ void wtinit() {
    u64 i = (u64)blockIdx.x * 256 + threadIdx.x;
    if (i < 8388608ull) GTQW[i] = (int)((i * 37ull) & 255ull);
    if (i < 262144ull) {
        GTAM[i] = (float)((u32)(i * 13ull) % 31u + 1u) * 0.03125f;
        u32 o = (u32)(i >> 6), r = (u32)(i & 63);
        float lb = (float)((int)((o*3u + r*7u) % 17u) - 8) * 0.015625f;
        float la = (float)((int)((o*5u + r*11u) % 19u) - 9) * 0.015625f;
        u16 hb, ha;
        asm("cvt.rn.f16.f32 %0, %1;" : "=h"(hb) : "f"(lb));
        asm("cvt.rn.f16.f32 %0, %1;" : "=h"(ha) : "f"(la));
        GLB[i] = hb;
        GLAT[i] = ha;
    }
}

__device__ __forceinline__ void ld_sub(u32 dst, const char* src, int tid, int iters) {
#pragma unroll
    for (int r = 0; r < 8; r++) {
        if (r >= iters) break;
        int i = tid + r * 256; int row = i >> 3, c = i & 7;
        u32 off = (u32)(row * 128 + ((c * 16) ^ ((row & 7) << 4)));
        asm volatile("cp.async.cg.shared.global.L2::256B [%0], [%1], 16;"
                     :: "r"(dst + off), "l"(src + (u64)row * 8192 + c * 16));
    }
}

// ---------------- gemm5 (R7 proven, single M-tile) ----------------
__device__ __forceinline__ void ld_stage(u32 sA, u32 sB, const char* xb,
                                         const char* wb, int tid) {
#pragma unroll
    for (int r = 0; r < 4; r++) {
        int i = tid + r * 256; int row = i >> 3, c = i & 7;
        u32 off = (u32)(row * 128 + ((c * 16) ^ ((row & 7) << 4)));
        asm volatile("cp.async.cg.shared.global.L2::256B [%0], [%1], 16;"
                     :: "r"(sA + off), "l"(xb + (u64)row * 8192 + c * 16));
    }
#pragma unroll
    for (int r = 0; r < 8; r++) {
        int i = tid + r * 256; int row = i >> 3, c = i & 7;
        u32 off = (u32)(row * 128 + ((c * 16) ^ ((row & 7) << 4)));
        asm volatile("cp.async.cg.shared.global.L2::256B [%0], [%1], 16;"
                     :: "r"(sB + off), "l"(wb + (u64)row * 8192 + c * 16));
    }
}

extern "C" __global__ void __launch_bounds__(256, 1)
gemm5(const char* __restrict__ X, const char* __restrict__ W,
      float* __restrict__ out) {
    extern __shared__ char sm[];
    u32 base = (sm2u32(sm) + 1023) & ~1023u;
    const u32 tptr = base;
    const u32 mb = base + 16;
    const u32 st0 = base + 1024;
    const int tid = threadIdx.x, wid = tid >> 5, lid = tid & 31;

    if (wid == 0)
        asm volatile("tcgen05.alloc.cta_group::1.sync.aligned.shared::cta.b32 [%0], %1;"
                     :: "r"(tptr), "r"(256u) : "memory");
    if (tid == 0) {
#pragma unroll
        for (int s = 0; s < 4; s++)
            asm volatile("mbarrier.init.shared.b64 [%0], %1;"
                         :: "r"(mb + s * 8), "r"(1u) : "memory");
    }
    __syncthreads();
    u32 tmem; asm volatile("ld.shared.b32 %0,[%1];" : "=r"(tmem) : "r"(tptr));

    const u64 DBASE = (2ull << 61) | (1ull << 46) | (64ull << 32) | (1ull << 16);
    const u32 IDESC = (1u << 4) | (32u << 17) | (8u << 24);

#pragma unroll 1
    for (int t = blockIdx.x; t < 1024; t += gridDim.x) {
        const int mBase = (t >> 4) * 128, nBase = (t & 15) * 256;
        const char* xt = X + (u64)mBase * 8192;
        const char* wt = W + (u64)nBase * 8192;

#pragma unroll
        for (int p = 0; p < 4; p++) {
            u32 sA = st0 + p * 49152;
            ld_stage(sA, sA + 16384, xt + p * 128, wt + p * 128, tid);
            asm volatile("cp.async.commit_group;" ::: "memory");
        }

#pragma unroll 1
        for (int kt = 0; kt < 64; kt++) {
            const int s = kt & 3;
            const u32 sA = st0 + s * 49152, sB = sA + 16384;
            asm volatile("cp.async.wait_group 3;" ::: "memory");
            __syncthreads();

            if (wid == 0) {
                u32 ep;
                asm volatile("{ .reg .pred p; elect.sync _|p, 0xFFFFFFFF; selp.b32 %0,1,0,p; }"
                             : "=r"(ep));
                if (ep) {
                    asm volatile("fence.proxy.async.shared::cta;" ::: "memory");
                    u64 ad = DBASE | ((u64)(sA >> 4) & 0x3FFF);
                    u64 bd = DBASE | ((u64)(sB >> 4) & 0x3FFF);
#pragma unroll
                    for (int q = 0; q < 4; q++) {
                        u32 en = (kt > 0 || q > 0) ? 1u : 0u;
                        asm volatile("{ .reg .pred p; setp.ne.u32 p, %5, 0; "
                            "tcgen05.mma.cta_group::1.kind::f16 [%0], %1, %2, %3, {%4,%4,%4,%4}, p; }"
                            :: "r"(tmem), "l"(ad + q * 2), "l"(bd + q * 2),
                               "r"(IDESC), "r"(0u), "r"(en) : "memory");
                    }
                    asm volatile("tcgen05.commit.cta_group::1.mbarrier::arrive::one.shared::cluster.b64 [%0];"
                                 :: "r"(mb + s * 8) : "memory");
                }
            }

            if (kt + 4 < 64) {
                u32 ph = (u32)((kt >> 2) & 1);
                MWAIT(mb + s * 8, ph);
                ld_stage(sA, sB, xt + (kt + 4) * 128, wt + (kt + 4) * 128, tid);
            }
            asm volatile("cp.async.commit_group;" ::: "memory");
        }

        MWAIT(mb + 24, 1u);
        asm volatile("tcgen05.fence::after_thread_sync;" ::: "memory");

        if (wid < 4) {
            float* dst = out + (u64)(mBase + wid * 32 + lid) * 4096 + nBase;
#pragma unroll
            for (int ch = 0; ch < 8; ch++) {
                u32 rr[32];
                LDTM32(rr, tmem + ch * 32);
                asm volatile("tcgen05.wait::ld.sync.aligned;" ::: "memory");
#pragma unroll
                for (int j = 0; j < 8; j++)
                    asm volatile("st.global.cs.v4.b32 [%0], {%1,%2,%3,%4};"
                                 :: "l"(dst + ch * 32 + j * 4),
                                    "r"(rr[4 * j]), "r"(rr[4 * j + 1]),
                                    "r"(rr[4 * j + 2]), "r"(rr[4 * j + 3]) : "memory");
            }
            asm volatile("tcgen05.fence::before_thread_sync;" ::: "memory");
        }
        __syncthreads();
    }

    __syncthreads();
    if (wid == 0) {
        asm volatile("tcgen05.relinquish_alloc_permit.cta_group::1.sync.aligned;");
        asm volatile("tcgen05.dealloc.cta_group::1.sync.aligned.b32 %0, %1;"
                     :: "r"(tmem), "r"(256u));
    }
}

// ---------------- gemm5b: 2 M-tiles per CTA (R8 pipeline) ----------------
extern "C" __global__ void __launch_bounds__(256, 1)
gemm5b(const char* __restrict__ X, const char* __restrict__ W,
       float* __restrict__ out) {
    extern __shared__ char sm[];
    u32 base = (sm2u32(sm) + 1023) & ~1023u;
    const u32 tptr = base;
    const u32 mb = base + 16;
    const u32 st0 = base + 1024;
    const int tid = threadIdx.x, wid = tid >> 5, lid = tid & 31;

    if (wid == 0)
        asm volatile("tcgen05.alloc.cta_group::1.sync.aligned.shared::cta.b32 [%0], %1;"
                     :: "r"(tptr), "r"(512u) : "memory");
    if (tid == 0) {
#pragma unroll
        for (int s = 0; s < 3; s++)
            asm volatile("mbarrier.init.shared.b64 [%0], %1;"
                         :: "r"(mb + s * 8), "r"(1u) : "memory");
    }
    __syncthreads();
    u32 tmem; asm volatile("ld.shared.b32 %0,[%1];" : "=r"(tmem) : "r"(tptr));

    const u64 DBASE = (2ull << 61) | (1ull << 46) | (64ull << 32) | (1ull << 16);
    const u32 IDESC = (1u << 4) | (32u << 17) | (8u << 24);

    int bp1 = 0, bp2 = 0;

#pragma unroll 1
    for (int t = blockIdx.x; t < 512; t += gridDim.x) {
        const int mBase = (t >> 4) * 256, nBase = (t & 15) * 256;
        const char* x0 = X + (u64)mBase * 8192;
        const char* x1 = x0 + 1048576;
        const char* wt = W + (u64)nBase * 8192;

#pragma unroll
        for (int p = 0; p < 3; p++) {
            u32 sA0 = st0 + p * 65536;
            ld_sub(sA0,         x0 + p * 128, tid, 4);
            ld_sub(sA0 + 16384, x1 + p * 128, tid, 4);
            ld_sub(sA0 + 32768, wt + p * 128, tid, 8);
            asm volatile("cp.async.commit_group;" ::: "memory");
        }

#pragma unroll 1
        for (int kt = 0; kt < 64; kt++) {
            const int kdiv = kt / 3;
            const int s = kt - kdiv * 3;
            const u32 sA0 = st0 + s * 65536, sA1 = sA0 + 16384, sB = sA0 + 32768;
            asm volatile("cp.async.wait_group 2;" ::: "memory");
            __syncthreads();

            if (wid == 0) {
                u32 ep;
                asm volatile("{ .reg .pred p; elect.sync _|p, 0xFFFFFFFF; selp.b32 %0,1,0,p; }"
                             : "=r"(ep));
                if (ep) {
                    asm volatile("fence.proxy.async.shared::cta;" ::: "memory");
                    u64 a0 = DBASE | ((u64)(sA0 >> 4) & 0x3FFF);
                    u64 a1 = DBASE | ((u64)(sA1 >> 4) & 0x3FFF);
                    u64 bd = DBASE | ((u64)(sB >> 4) & 0x3FFF);
#pragma unroll
                    for (int q = 0; q < 4; q++) {
                        u32 en = (kt > 0 || q > 0) ? 1u : 0u;
                        asm volatile("{ .reg .pred p; setp.ne.u32 p, %5, 0; "
                            "tcgen05.mma.cta_group::1.kind::f16 [%0], %1, %2, %3, {%4,%4,%4,%4}, p; }"
                            :: "r"(tmem), "l"(a0 + q * 2), "l"(bd + q * 2),
                               "r"(IDESC), "r"(0u), "r"(en) : "memory");
                        asm volatile("{ .reg .pred p; setp.ne.u32 p, %5, 0; "
                            "tcgen05.mma.cta_group::1.kind::f16 [%0], %1, %2, %3, {%4,%4,%4,%4}, p; }"
                            :: "r"(tmem + 256), "l"(a1 + q * 2), "l"(bd + q * 2),
                               "r"(IDESC), "r"(0u), "r"(en) : "memory");
                    }
                    asm volatile("tcgen05.commit.cta_group::1.mbarrier::arrive::one.shared::cluster.b64 [%0];"
                                 :: "r"(mb + s * 8) : "memory");
                }
            }

            if (kt + 3 < 64) {
                int bps = (s == 0) ? 0 : ((s == 1) ? bp1 : bp2);
                u32 ph = (u32)(bps ^ (kdiv & 1));
                MWAIT(mb + s * 8, ph);
                ld_sub(sA0, x0 + (kt + 3) * 128, tid, 4);
                ld_sub(sA1, x1 + (kt + 3) * 128, tid, 4);
                ld_sub(sB,  wt + (kt + 3) * 128, tid, 8);
            }
            asm volatile("cp.async.commit_group;" ::: "memory");
        }

        MWAIT(mb, 1u);
        asm volatile("tcgen05.fence::after_thread_sync;" ::: "memory");

        {
            const int half = wid >> 2, wr = wid & 3;
            float* dst = out + (u64)(mBase + half * 128 + wr * 32 + lid) * 4096 + nBase;
            const u32 tm = tmem + half * 256;
#pragma unroll
            for (int ch = 0; ch < 8; ch++) {
                u32 rr[32];
                LDTM32(rr, tm + ch * 32);
                asm volatile("tcgen05.wait::ld.sync.aligned;" ::: "memory");
#pragma unroll
                for (int j = 0; j < 8; j++)
                    asm volatile("st.global.cs.v4.b32 [%0], {%1,%2,%3,%4};"
                                 :: "l"(dst + ch * 32 + j * 4),
                                    "r"(rr[4 * j]), "r"(rr[4 * j + 1]),
                                    "r"(rr[4 * j + 2]), "r"(rr[4 * j + 3]) : "memory");
            }
            asm volatile("tcgen05.fence::before_thread_sync;" ::: "memory");
        }
        __syncthreads();
        bp1 ^= 1; bp2 ^= 1;
    }

    __syncthreads();
    if (wid == 0) {
        asm volatile("tcgen05.relinquish_alloc_permit.cta_group::1.sync.aligned;");
        asm volatile("tcgen05.dealloc.cta_group::1.sync.aligned.b32 %0, %1;"
                     :: "r"(tmem), "r"(512u));
    }
}

// ---------------- gemm5c: 2 M-tiles, DECOUPLED pipeline ----------------
// Load lead = 2 (= S-1): loads for ktile kt+2 go into slot (kt-1)%3, guarded
// by commit(kt-1) which has normally already completed -> tensor pipe never
// drains between iterations.
extern "C" __global__ void __launch_bounds__(256, 1)
gemm5c(const char* __restrict__ X, const char* __restrict__ W,
       float* __restrict__ out) {
    extern __shared__ char sm[];
    u32 base = (sm2u32(sm) + 1023) & ~1023u;
    const u32 tptr = base;
    const u32 mb = base + 16;
    const u32 st0 = base + 1024;
    const int tid = threadIdx.x, wid = tid >> 5, lid = tid & 31;

    if (wid == 0)
        asm volatile("tcgen05.alloc.cta_group::1.sync.aligned.shared::cta.b32 [%0], %1;"
                     :: "r"(tptr), "r"(512u) : "memory");
    if (tid == 0) {
#pragma unroll
        for (int s = 0; s < 3; s++)
            asm volatile("mbarrier.init.shared.b64 [%0], %1;"
                         :: "r"(mb + s * 8), "r"(1u) : "memory");
    }
    __syncthreads();
    u32 tmem; asm volatile("ld.shared.b32 %0,[%1];" : "=r"(tmem) : "r"(tptr));

    const u64 DBASE = (2ull << 61) | (1ull << 46) | (64ull << 32) | (1ull << 16);
    const u32 IDESC = (1u << 4) | (32u << 17) | (8u << 24);

    int bp1 = 0, bp2 = 0;

#pragma unroll 1
    for (int t = blockIdx.x; t < 512; t += gridDim.x) {
        const int mBase = (t >> 4) * 256, nBase = (t & 15) * 256;
        const char* x0 = X + (u64)mBase * 8192;
        const char* x1 = x0 + 1048576;
        const char* wt = W + (u64)nBase * 8192;

        // prologue: ktiles 0,1 into slots 0,1
#pragma unroll
        for (int p = 0; p < 2; p++) {
            u32 sA0 = st0 + p * 65536;
            ld_sub(sA0,         x0 + p * 128, tid, 4);
            ld_sub(sA0 + 16384, x1 + p * 128, tid, 4);
            ld_sub(sA0 + 32768, wt + p * 128, tid, 8);
            asm volatile("cp.async.commit_group;" ::: "memory");
        }

#pragma unroll 1
        for (int kt = 0; kt < 64; kt++) {
            const int kdiv = kt / 3;
            const int s = kt - kdiv * 3;
            const u32 sA0 = st0 + s * 65536, sA1 = sA0 + 16384, sB = sA0 + 32768;
            asm volatile("cp.async.wait_group 1;" ::: "memory");
            __syncthreads();

            if (wid == 0) {
                u32 ep;
                asm volatile("{ .reg .pred p; elect.sync _|p, 0xFFFFFFFF; selp.b32 %0,1,0,p; }"
                             : "=r"(ep));
                if (ep) {
                    asm volatile("fence.proxy.async.shared::cta;" ::: "memory");
                    u64 a0 = DBASE | ((u64)(sA0 >> 4) & 0x3FFF);
                    u64 a1 = DBASE | ((u64)(sA1 >> 4) & 0x3FFF);
                    u64 bd = DBASE | ((u64)(sB >> 4) & 0x3FFF);
#pragma unroll
                    for (int q = 0; q < 4; q++) {
                        u32 en = (kt > 0 || q > 0) ? 1u : 0u;
                        asm volatile("{ .reg .pred p; setp.ne.u32 p, %5, 0; "
                            "tcgen05.mma.cta_group::1.kind::f16 [%0], %1, %2, %3, {%4,%4,%4,%4}, p; }"
                            :: "r"(tmem), "l"(a0 + q * 2), "l"(bd + q * 2),
                               "r"(IDESC), "r"(0u), "r"(en) : "memory");
                        asm volatile("{ .reg .pred p; setp.ne.u32 p, %5, 0; "
                            "tcgen05.mma.cta_group::1.kind::f16 [%0], %1, %2, %3, {%4,%4,%4,%4}, p; }"
                            :: "r"(tmem + 256), "l"(a1 + q * 2), "l"(bd + q * 2),
                               "r"(IDESC), "r"(0u), "r"(en) : "memory");
                    }
                    asm volatile("tcgen05.commit.cta_group::1.mbarrier::arrive::one.shared::cluster.b64 [%0];"
                                 :: "r"(mb + s * 8) : "memory");
                }
            }

            if (kt + 2 < 64) {
                const int sd = (kt + 2) - ((kt + 2) / 3) * 3;  // == (kt-1)%3 for kt>=1
                const u32 dA0 = st0 + sd * 65536;
                if (kt >= 1) {
                    const int kp = kt - 1;
                    const int kdv = kp / 3;
                    const int sp = kp - kdv * 3;   // == sd
                    int bps = (sp == 0) ? 0 : ((sp == 1) ? bp1 : bp2);
                    u32 ph = (u32)(bps ^ (kdv & 1));
                    MWAIT(mb + sp * 8, ph);
                }
                ld_sub(dA0,         x0 + (kt + 2) * 128, tid, 4);
                ld_sub(dA0 + 16384, x1 + (kt + 2) * 128, tid, 4);
                ld_sub(dA0 + 32768, wt + (kt + 2) * 128, tid, 8);
            }
            asm volatile("cp.async.commit_group;" ::: "memory");
        }

        // drain: commit of kt=63 (slot 0, index 21 -> parity 1; slot0 base 0)
        MWAIT(mb, 1u);
        asm volatile("tcgen05.fence::after_thread_sync;" ::: "memory");

        {
            const int half = wid >> 2, wr = wid & 3;
            float* dst = out + (u64)(mBase + half * 128 + wr * 32 + lid) * 4096 + nBase;
            const u32 tm = tmem + half * 256;
#pragma unroll
            for (int ch = 0; ch < 8; ch++) {
                u32 rr[32];
                LDTM32(rr, tm + ch * 32);
                asm volatile("tcgen05.wait::ld.sync.aligned;" ::: "memory");
#pragma unroll
                for (int j = 0; j < 8; j++)
                    asm volatile("st.global.cs.v4.b32 [%0], {%1,%2,%3,%4};"
                                 :: "l"(dst + ch * 32 + j * 4),
                                    "r"(rr[4 * j]), "r"(rr[4 * j + 1]),
                                    "r"(rr[4 * j + 2]), "r"(rr[4 * j + 3]) : "memory");
            }
            asm volatile("tcgen05.fence::before_thread_sync;" ::: "memory");
        }
        __syncthreads();
        bp1 ^= 1; bp2 ^= 1;   // slots 1,2: 21 commits/tile; slot 0: 22
    }

    __syncthreads();
    if (wid == 0) {
        asm volatile("tcgen05.relinquish_alloc_permit.cta_group::1.sync.aligned;");
        asm volatile("tcgen05.dealloc.cta_group::1.sync.aligned.b32 %0, %1;"
                     :: "r"(tmem), "r"(512u));
    }
}

// ---------------- wbuild: fused LoRA GEMM + NF4 dequant ----------------
extern "C" __global__ void __launch_bounds__(256, 1)
wbuild(const int* __restrict__ qw, const float* __restrict__ am,
       const u16* __restrict__ lb, const u16* __restrict__ lat,
       u16* __restrict__ w) {
    extern __shared__ char sm[];
    u32 base = (sm2u32(sm) + 1023) & ~1023u;
    const u32 tptr = base;
    const u32 mb = base + 16;
    const u32 sa = base + 1024;
    const u32 sb = sa + 16384;
    const int tid = threadIdx.x, wid = tid >> 5, lid = tid & 31;
    const int ti = blockIdx.x;
    const int o0 = (ti >> 4) * 128, i0 = (ti & 15) * 256;

    if (wid == 0)
        asm volatile("tcgen05.alloc.cta_group::1.sync.aligned.shared::cta.b32 [%0], %1;"
                     :: "r"(tptr), "r"(256u) : "memory");
    if (tid == 0)
        asm volatile("mbarrier.init.shared.b64 [%0], %1;" :: "r"(mb), "r"(1u) : "memory");
    __syncthreads();
    u32 tmem; asm volatile("ld.shared.b32 %0,[%1];" : "=r"(tmem) : "r"(tptr));

#pragma unroll
    for (int r = 0; r < 4; r++) {
        int i = tid + r * 256; int row = i >> 3, c = i & 7;
        u32 off = (u32)(row * 128 + ((c * 16) ^ ((row & 7) << 4)));
        asm volatile("cp.async.cg.shared.global [%0], [%1], 16;"
                     :: "r"(sa + off), "l"((const char*)lb + (u64)(o0 + row) * 128 + c * 16));
    }
#pragma unroll
    for (int r = 0; r < 8; r++) {
        int i = tid + r * 256; int row = i >> 3, c = i & 7;
        u32 off = (u32)(row * 128 + ((c * 16) ^ ((row & 7) << 4)));
        asm volatile("cp.async.cg.shared.global [%0], [%1], 16;"
                     :: "r"(sb + off), "l"((const char*)lat + (u64)(i0 + row) * 128 + c * 16));
    }
    asm volatile("cp.async.commit_group;" ::: "memory");
    asm volatile("cp.async.wait_group 0;" ::: "memory");
    __syncthreads();

    const u64 DBASE = (2ull << 61) | (1ull << 46) | (64ull << 32) | (1ull << 16);
    const u32 IDESC = (1u << 4) | (32u << 17) | (8u << 24);

    if (wid == 0) {
        u32 ep;
        asm volatile("{ .reg .pred p; elect.sync _|p, 0xFFFFFFFF; selp.b32 %0,1,0,p; }"
                     : "=r"(ep));
        if (ep) {
            asm volatile("fence.proxy.async.shared::cta;" ::: "memory");
            u64 ad = DBASE | ((u64)(sa >> 4) & 0x3FFF);
            u64 bd = DBASE | ((u64)(sb >> 4) & 0x3FFF);
#pragma unroll
            for (int q = 0; q < 4; q++) {
                u32 en = (q > 0) ? 1u : 0u;
                asm volatile("{ .reg .pred p; setp.ne.u32 p, %5, 0; "
                    "tcgen05.mma.cta_group::1.kind::f16 [%0], %1, %2, %3, {%4,%4,%4,%4}, p; }"
                    :: "r"(tmem), "l"(ad + q * 2), "l"(bd + q * 2),
                       "r"(IDESC), "r"(0u), "r"(en) : "memory");
            }
            asm volatile("tcgen05.commit.cta_group::1.mbarrier::arrive::one.shared::cluster.b64 [%0];"
                         :: "r"(mb) : "memory");
        }
    }
    __syncthreads();
    MWAIT(mb, 0u);
    asm volatile("tcgen05.fence::after_thread_sync;" ::: "memory");

    const int half = wid >> 2, wr = wid & 3;
    const int o = o0 + wr * 32 + lid;
#pragma unroll
    for (int c4 = 0; c4 < 4; c4++) {
        u32 rr[32];
        LDTM32(rr, tmem + half * 128 + c4 * 32);
        asm volatile("tcgen05.wait::ld.sync.aligned;" ::: "memory");
        const u64 k = (u64)o * 4096 + (u64)(i0 + half * 128 + c4 * 32);
        const float a = am[k >> 6];
        const int4* qp = (const int4*)qw + (k >> 3);
        u32 ov[16];
#pragma unroll
        for (int u = 0; u < 4; u++) {
            int4 qv = qp[u];
            int e[8] = {qv.x & 15, (qv.x >> 4) & 15, qv.y & 15, (qv.y >> 4) & 15,
                        qv.z & 15, (qv.z >> 4) & 15, qv.w & 15, (qv.w >> 4) & 15};
#pragma unroll
            for (int j = 0; j < 4; j++) {
                union { u32 u_; float f_; } c0, c1;
                c0.u_ = rr[u * 8 + 2 * j];
                c1.u_ = rr[u * 8 + 2 * j + 1];
                float w0 = NF4D[e[2 * j]] * a + c0.f_;
                float w1 = NF4D[e[2 * j + 1]] * a + c1.f_;
                asm("cvt.rn.f16x2.f32 %0, %1, %2;" : "=r"(ov[u * 4 + j]) : "f"(w1), "f"(w0));
            }
        }
        char* wp = (char*)w + k * 2;
#pragma unroll
        for (int j = 0; j < 4; j++)
            asm volatile("st.global.cs.v4.b32 [%0], {%1,%2,%3,%4};"
                         :: "l"(wp + j * 16), "r"(ov[4 * j]), "r"(ov[4 * j + 1]),
                            "r"(ov[4 * j + 2]), "r"(ov[4 * j + 3]) : "memory");
    }
    asm volatile("tcgen05.fence::before_thread_sync;" ::: "memory");
    __syncthreads();
    if (wid == 0) {
        asm volatile("tcgen05.relinquish_alloc_permit.cta_group::1.sync.aligned;");
        asm volatile("tcgen05.dealloc.cta_group::1.sync.aligned.b32 %0, %1;"
                     :: "r"(tmem), "r"(256u));
    }
}
)NVSRC";

// --- driver/nvrtc plumbing ---
typedef int (*nvrtcCreateProgram_t)(void**, const char*, const char*, int,
                                    const char* const*, const char* const*);
typedef int (*nvrtcCompileProgram_t)(void*, int, const char* const*);
typedef int (*nvrtcGetCUBINSize_t)(void*, size_t*);
typedef int (*nvrtcGetCUBIN_t)(void*, char*);
typedef int (*cuInit_t)(unsigned);
typedef int (*cuDevicePrimaryCtxRetain_t)(void**, int);
typedef int (*cuCtxSetCurrent_t)(void*);
typedef int (*cuModuleLoadDataEx_t)(void**, const void*, unsigned, int*, void**);
typedef int (*cuModuleGetFunction_t)(void**, void*, const char*);
typedef int (*cuModuleGetGlobal_t)(unsigned long long*, size_t*, void*, const char*);
typedef int (*cuFuncSetAttribute_t)(void*, int, int);
typedef int (*cuLaunchKernel_t)(void*, unsigned, unsigned, unsigned,
                                unsigned, unsigned, unsigned,
                                unsigned, void*, void**, void**);
typedef int (*cuCtxSynchronize_t)(void);
typedef int (*cuMemcpyDtoH_t)(void*, unsigned long long, size_t);

#if defined(CUDA_API_PER_THREAD_DEFAULT_STREAM) || defined(__CUDA_API_PER_THREAD_DEFAULT_STREAM)
#define DRV_STREAM ((void*)0x2)
#else
#define DRV_STREAM ((void*)0x1)
#endif

static bool g_ok_gemm = false, g_ok_wb = false;
static cuLaunchKernel_t p_cuLaunchKernel = nullptr;
static void* g_fn_gemm = nullptr;
static void* g_fn_wbuild = nullptr;
static unsigned long long g_gx = 0, g_gw = 0, g_glb = 0, g_glat = 0;
constexpr int SMEM5 = 198656;
constexpr int SMEMW = 51200;

static float h2f(uint16_t h) {
    uint32_t s = (h >> 15) & 1, e = (h >> 10) & 31, m = h & 1023;
    uint32_t f;
    if (e == 0) {
        if (m == 0) f = s << 31;
        else {
            e = 127 - 15 + 1;
            while (!(m & 1024)) { m <<= 1; e--; }
            m &= 1023;
            f = (s << 31) | (e << 23) | (m << 13);
        }
    } else if (e == 31) f = (s << 31) | 0x7F800000 | (m << 13);
    else f = (s << 31) | ((e - 15 + 127) << 23) | (m << 13);
    float r; memcpy(&r, &f, 4); return r;
}

static bool try_init_tcgen05() {
    void* hcu = dlopen("libcuda.so.1", RTLD_NOW | RTLD_GLOBAL);
    if (!hcu) hcu = dlopen("libcuda.so", RTLD_NOW | RTLD_GLOBAL);
    if (!hcu) return false;
    void* hnv = dlopen("libnvrtc.so.13", RTLD_NOW | RTLD_GLOBAL);
    if (!hnv) hnv = dlopen("libnvrtc.so", RTLD_NOW | RTLD_GLOBAL);
    if (!hnv) hnv = dlopen("libnvrtc.so.12", RTLD_NOW | RTLD_GLOBAL);
    if (!hnv) return false;

    auto nCreate  = (nvrtcCreateProgram_t)dlsym(hnv, "nvrtcCreateProgram");
    auto nCompile = (nvrtcCompileProgram_t)dlsym(hnv, "nvrtcCompileProgram");
    auto nCbSize  = (nvrtcGetCUBINSize_t)dlsym(hnv, "nvrtcGetCUBINSize");
    auto nCb      = (nvrtcGetCUBIN_t)dlsym(hnv, "nvrtcGetCUBIN");
    auto cInit    = (cuInit_t)dlsym(hcu, "cuInit");
    auto cRetain  = (cuDevicePrimaryCtxRetain_t)dlsym(hcu, "cuDevicePrimaryCtxRetain");
    auto cSetCur  = (cuCtxSetCurrent_t)dlsym(hcu, "cuCtxSetCurrent");
    auto cModLoad = (cuModuleLoadDataEx_t)dlsym(hcu, "cuModuleLoadDataEx");
    auto cGetFn   = (cuModuleGetFunction_t)dlsym(hcu, "cuModuleGetFunction");
    auto cGetGlb  = (cuModuleGetGlobal_t)dlsym(hcu, "cuModuleGetGlobal_v2");
    auto cSetAttr = (cuFuncSetAttribute_t)dlsym(hcu, "cuFuncSetAttribute");
    auto cLaunch  = (cuLaunchKernel_t)dlsym(hcu, "cuLaunchKernel");
    auto cSync    = (cuCtxSynchronize_t)dlsym(hcu, "cuCtxSynchronize");
    auto cD2H     = (cuMemcpyDtoH_t)dlsym(hcu, "cuMemcpyDtoH_v2");
    if (!nCreate || !nCompile || !nCbSize || !nCb || !cInit || !cRetain ||
        !cSetCur || !cModLoad || !cGetFn || !cGetGlb || !cSetAttr ||
        !cLaunch || !cSync || !cD2H)
        return false;

    if (cInit(0)) return false;
    void* ctx = nullptr;
    if (cRetain(&ctx, 0)) return false;
    if (cSetCur(ctx)) return false;

    void* prog = nullptr;
    if (nCreate(&prog, NVRTC_SRC, "gemm5.cu", 0, nullptr, nullptr)) return false;
    const char* opts[] = {"--gpu-architecture=sm_103a"};
    if (nCompile(prog, 1, opts)) return false;
    size_t cbsz = 0;
    if (nCbSize(prog, &cbsz) || cbsz == 0) return false;
    static char* cubin = new char[cbsz];
    if (nCb(prog, cubin)) return false;

    void* mod = nullptr;
    if (cModLoad(&mod, cubin, 0, nullptr, nullptr)) return false;
    void *fG5 = nullptr, *fG5b = nullptr, *fG5c = nullptr;
    void *fInit = nullptr, *fWb = nullptr, *fWti = nullptr;
    if (cGetFn(&fG5, mod, "gemm5")) return false;
    if (cGetFn(&fG5b, mod, "gemm5b")) return false;
    if (cGetFn(&fG5c, mod, "gemm5c")) return false;
    if (cGetFn(&fInit, mod, "initt")) return false;
    if (cGetFn(&fWb, mod, "wbuild")) return false;
    if (cGetFn(&fWti, mod, "wtinit")) return false;
    unsigned long long gx = 0, gw = 0, gout = 0, glb = 0, glat = 0, gtqw = 0, gtam = 0;
    size_t sz;
    if (cGetGlb(&gx, &sz, mod, "GX")) return false;
    if (cGetGlb(&gw, &sz, mod, "GW")) return false;
    if (cGetGlb(&gout, &sz, mod, "GOUT")) return false;
    if (cGetGlb(&glb, &sz, mod, "GLB")) return false;
    if (cGetGlb(&glat, &sz, mod, "GLAT")) return false;
    if (cGetGlb(&gtqw, &sz, mod, "GTQW")) return false;
    if (cGetGlb(&gtam, &sz, mod, "GTAM")) return false;
    if (cSetAttr(fG5, 8, SMEM5)) return false;
    if (cSetAttr(fG5b, 8, SMEM5)) return false;
    if (cSetAttr(fG5c, 8, SMEM5)) return false;
    if (cSetAttr(fWb, 8, SMEMW)) return false;

    p_cuLaunchKernel = cLaunch;
    g_gx = gx; g_gw = gw; g_glb = glb; g_glat = glat;

    // ---- gemm self-test (exact integer grid) ----
    if (cLaunch(fInit, 131072, 1, 1, 256, 1, 1, 0, DRV_STREAM, nullptr, nullptr))
        return false;
    static float row[OUT_F];
    const int ms[4] = {0, 97, 4095, 8191};
    auto test_gemm = [&](void* fn) -> bool {
        unsigned long long px = gx, pw = gw, po = gout;
        void* args[3] = {&px, &pw, &po};
        if (cLaunch(fn, 148, 1, 1, 256, 1, 1, SMEM5, DRV_STREAM, args, nullptr))
            return false;
        if (cSync()) return false;
        for (int ri = 0; ri < 4; ri++) {
            int m = ms[ri];
            if (cD2H(row, gout + (unsigned long long)m * OUT_F * 4, OUT_F * 4))
                return false;
            for (int n = 0; n < OUT_F; n++) {
                float ref = 0.0f;
                for (int k = 0; k < IN_F; k++) {
                    int av = (k * 131 + m * 7) % 9 - 4;
                    int bv = (k * 17 + n * 3) % 7 - 3;
                    ref += (av * 0.25f) * (bv * 0.25f);
                }
                if (fabsf(row[n] - ref) > 0.01f) return false;
            }
        }
        return true;
    };
    if (test_gemm(fG5c)) { g_fn_gemm = fG5c; g_ok_gemm = true; }
    else if (test_gemm(fG5b)) { g_fn_gemm = fG5b; g_ok_gemm = true; }
    else if (test_gemm(fG5)) { g_fn_gemm = fG5; g_ok_gemm = true; }
    if (!g_ok_gemm) return false;

    // ---- wbuild self-test ----
    do {
        if (cLaunch(fWti, 32768, 1, 1, 256, 1, 1, 0, DRV_STREAM, nullptr, nullptr))
            break;
        unsigned long long pq = gtqw, pa = gtam, pl = glb, pt = glat, pw2 = gw;
        void* args[5] = {&pq, &pa, &pl, &pt, &pw2};
        if (cLaunch(fWb, 512, 1, 1, 256, 1, 1, SMEMW, DRV_STREAM, args, nullptr))
            break;
        if (cSync()) break;
        static uint16_t wrow[IN_F];
        const int os[4] = {0, 1, 255, 4095};
        bool ok = true;
        for (int oi = 0; oi < 4 && ok; oi++) {
            int o = os[oi];
            if (cD2H(wrow, gw + (unsigned long long)o * IN_F * 2, IN_F * 2)) { ok = false; break; }
            for (int i = 0; i < IN_F; i++) {
                uint64_t k = (uint64_t)o * 4096 + i;
                uint64_t t = k >> 1;
                int qv = (int)((t * 37ull) & 255ull);
                int nib = (k & 1) ? (qv >> 4) & 15 : qv & 15;
                float a = (float)(((uint32_t)((k >> 6) * 13ull)) % 31u + 1u) * 0.03125f;
                float lora = 0.0f;
                for (int r = 0; r < 64; r++) {
                    float lb = (float)((int)(((uint32_t)o * 3u + r * 7u) % 17u) - 8) * 0.015625f;
                    float la = (float)((int)(((uint32_t)i * 5u + r * 11u) % 19u) - 9) * 0.015625f;
                    lora += lb * la;
                }
                float ref = NF4H[nib] * a + lora;
                if (fabsf(h2f(wrow[i]) - ref) > 0.01f) { ok = false; break; }
            }
        }
        if (ok) { g_fn_wbuild = fWb; g_ok_wb = true; }
    } while (0);

    return true;
}

__attribute__((constructor))
static void _init_drv() {
    try_init_tcgen05();
}

// ---------------------------------------------------------------------------
extern "C" void kernel_launch(void* const* d_in, const int* in_sizes, int n_in,
                              void* d_out, int out_size) {
    const float* x  = (const float*)d_in[0];
    const int*   qw = (const int*)d_in[1];
    const float* am = (const float*)d_in[2];
    const float* lA = (const float*)d_in[3];
    const float* lB = (const float*)d_in[4];
    float*       out = (float*)d_out;

    (void)in_sizes; (void)n_in; (void)out_size;

    if (g_ok_gemm) {
        __half* xh = (__half*)(uintptr_t)g_gx;
        __half* wh = (__half*)(uintptr_t)g_gw;

        convert_x_kernel<<<(M_ROWS * IN_F / 8) / 256, 256>>>(x, xh);

        if (g_ok_wb) {
            cvt_lb_kernel<<<256, 256>>>(lB, (__half*)(uintptr_t)g_glb);
            cvt_lat_kernel<<<64, 256>>>(lA, (__half*)(uintptr_t)g_glat);
            unsigned long long pq = (unsigned long long)(uintptr_t)qw;
            unsigned long long pa = (unsigned long long)(uintptr_t)am;
            unsigned long long pl = g_glb, pt = g_glat, pw = g_gw;
            void* args[5] = {&pq, &pa, &pl, &pt, &pw};
            p_cuLaunchKernel(g_fn_wbuild, 512, 1, 1, 256, 1, 1, SMEMW,
                             DRV_STREAM, args, nullptr);
        } else {
            build_weff_kernel<<<dim3(IN_F / 128, OUT_F / 64), 256>>>(qw, am, lA, lB, wh);
        }

        unsigned long long px = g_gx, pw2 = g_gw;
        void* po = (void*)out;
        void* args[3] = {&px, &pw2, &po};
        p_cuLaunchKernel(g_fn_gemm, 148, 1, 1, 256, 1, 1, SMEM5,
                         DRV_STREAM, args, nullptr);
    } else {
        __half* xh; __half* wh;
        cudaGetSymbolAddress((void**)&xh, g_Xh);
        cudaGetSymbolAddress((void**)&wh, g_Wh);
        convert_x_kernel<<<(M_ROWS * IN_F / 8) / 256, 256>>>(x, xh);
        build_weff_kernel<<<dim3(IN_F / 128, OUT_F / 64), 256>>>(qw, am, lA, lB, wh);
        cudaFuncSetAttribute(gemm_f16_kernel,
                             cudaFuncAttributeMaxDynamicSharedMemorySize, SMEM_TOTAL);
        gemm_f16_kernel<<<148, 512, SMEM_TOTAL>>>(xh, wh, out);
    }
}